// round 11
// baseline (speedup 1.0000x reference)
#include <cuda_runtime.h>
#include <cuda_fp16.h>
#include <cstdint>

#define N 2048
#define E 4
#define C 4
#define F 128      // W_OUT
#define WIN 256
#define NNSZ ((size_t)N * N)
#define NFSZ ((size_t)N * F)
#define SPB_SCALE 1024.0f
#define SPB_UNSCALE (1.0f / 1024.0f)

// ---------------- scratch (static device globals; no allocation) ----------------
__device__ float g_fw[3][16];            // softmaxed weights: [0]=fw1, [1]=fw2, [2]=fw3
__device__ float g_support[N * F];       // X @ gcn_w              [n][f]
__device__ float g_part[16 * E * N];     // per-chunk partial raw rowsums
__device__ float g_v1[C * N];
__device__ float g_v2[C * N];
__device__ float g_v3[C * N];
__device__ float g_d[C * N];             // deg^-1/2
__device__ float g_Sp[C * N * F];        // diag(d)@support natural [c][n][f] fp32
// fp16 fragment-order planes
__device__ __align__(16) __half g_SpBH[C * N * F];   // B plane stage 0 (scaled x1024)
__device__ __align__(16) __half g_T0BH[C * N * F];   // B plane stage 1 (natural)
__device__ __align__(16) __half g_T1BH[C * N * F];   // B plane stage 2 (natural)
// premixed A planes fp16: [stage*4+c], unit = m16 x k16 (256 halfs); unit idx = mt*128 + kt
__device__ __align__(16) __half g_AmH[12 * NNSZ];    // 96 MB

__device__ __forceinline__ uint32_t pkh(float a, float b) {
    __half2 h = __floats2half2_rn(a, b);
    return *(uint32_t*)&h;
}

// mma.m16n8k16 f16 -> f32 accum
__device__ __forceinline__ void mma_f16(float& d0, float& d1, float& d2, float& d3,
                                        uint32_t a0, uint32_t a1, uint32_t a2, uint32_t a3,
                                        uint32_t b0, uint32_t b1) {
    asm volatile(
        "mma.sync.aligned.m16n8k16.row.col.f32.f16.f16.f32 "
        "{%0,%1,%2,%3}, {%4,%5,%6,%7}, {%8,%9}, {%0,%1,%2,%3};"
        : "+f"(d0), "+f"(d1), "+f"(d2), "+f"(d3)
        : "r"(a0), "r"(a1), "r"(a2), "r"(a3), "r"(b0), "r"(b1));
}

// ---------------- tiny: softmax of 4x4 weight rows ----------------
__global__ void k_softmax(const float* __restrict__ w1,
                          const float* __restrict__ w2,
                          const float* __restrict__ w3) {
    int t = threadIdx.x;
    if (t >= 12) return;
    int mat = t >> 2, row = t & 3;
    const float* src = (mat == 0) ? w1 : (mat == 1) ? w2 : w3;
    float a0 = src[row * 4 + 0], a1 = src[row * 4 + 1];
    float a2 = src[row * 4 + 2], a3 = src[row * 4 + 3];
    float mx = fmaxf(fmaxf(a0, a1), fmaxf(a2, a3));
    float e0 = expf(a0 - mx), e1 = expf(a1 - mx), e2 = expf(a2 - mx), e3 = expf(a3 - mx);
    float inv = 1.0f / (e0 + e1 + e2 + e3);
    g_fw[mat][row * 4 + 0] = e0 * inv;
    g_fw[mat][row * 4 + 1] = e1 * inv;
    g_fw[mat][row * 4 + 2] = e2 * inv;
    g_fw[mat][row * 4 + 3] = e3 * inv;
}

// ---------------- support = X @ gcn_w ----------------
__global__ void __launch_bounds__(256) k_support(const float* __restrict__ X,
                                                 const float* __restrict__ W) {
    __shared__ float Xs[32][WIN];
    int tid = threadIdx.x;
    int row0 = blockIdx.x * 32;
    const float4* Xg = (const float4*)(X + (size_t)row0 * WIN);
    float4* Xs4 = (float4*)&Xs[0][0];
    #pragma unroll
    for (int j = 0; j < (32 * WIN / 4) / 256; j++)
        Xs4[tid + j * 256] = Xg[tid + j * 256];
    __syncthreads();
    int f = tid & 127, ty = tid >> 7;
    float acc[16];
    #pragma unroll
    for (int r = 0; r < 16; r++) acc[r] = 0.f;
    for (int k = 0; k < WIN; k++) {
        float w = W[k * F + f];
        #pragma unroll
        for (int r = 0; r < 16; r++)
            acc[r] = fmaf(Xs[ty * 16 + r][k], w, acc[r]);
    }
    #pragma unroll
    for (int r = 0; r < 16; r++)
        g_support[(size_t)(row0 + ty * 16 + r) * F + f] = acc[r];
}

// ---------------- premix fp16: one (band, chunk) tile per CTA ----------------
// grid: (16 chunks, 128 bands), 256 threads. 12 fp16 frag planes + partial rowsums.
__global__ void __launch_bounds__(256) k_premix_h(const float* __restrict__ A) {
    __shared__ float As[4][16][132];
    __shared__ float wsm[48];
    const int tid = threadIdx.x, lane = tid & 31, warp = tid >> 5;
    const int g = lane >> 2, cl = lane & 3;
    const int ch = blockIdx.x;            // 0..15 (128-col chunk)
    const int band = blockIdx.y;          // 0..127 (16-row band)
    const int n0 = band * 16, m0 = ch * 128;

    if (tid < 48) wsm[tid] = ((const float*)g_fw)[tid];
    #pragma unroll
    for (int e = 0; e < 4; e++)
        #pragma unroll
        for (int j = 0; j < 2; j++) {
            int idx = tid + j * 256;
            int r = idx >> 5, m4 = idx & 31;
            *(float4*)&As[e][r][m4 * 4] =
                *(const float4*)(A + (size_t)e * NNSZ + (size_t)(n0 + r) * N + m0 + m4 * 4);
        }
    __syncthreads();

    // raw partial rowsums -> g_part[ch][e][n]
    {
        int e = tid >> 6, r = (tid >> 2) & 15, part = tid & 3;
        float s = 0.f;
        #pragma unroll
        for (int i = 0; i < 32; i++) s += As[e][r][part * 32 + i];
        s += __shfl_xor_sync(0xffffffffu, s, 1);
        s += __shfl_xor_sync(0xffffffffu, s, 2);
        if (part == 0) g_part[(size_t)ch * (4 * N) + e * N + n0 + r] = s;
    }

    // 12 planes x 8 k16-units = 96 warp tasks
    for (int task = warp; task < 96; task += 8) {
        int plane = task >> 3, ktl = task & 7;
        int s = plane >> 2;
        const float* wv = wsm + (2 - s) * 16 + (plane & 3) * 4;
        int cols[4] = {ktl * 16 + 2 * cl, ktl * 16 + 2 * cl + 1,
                       ktl * 16 + 2 * cl + 8, ktl * 16 + 2 * cl + 9};
        float m[8];
        #pragma unroll
        for (int j = 0; j < 4; j++) {
            float lo = 0.f, hi = 0.f;
            #pragma unroll
            for (int e = 0; e < 4; e++) {
                lo = fmaf(wv[e], As[e][g][cols[j]], lo);
                hi = fmaf(wv[e], As[e][g + 8][cols[j]], hi);
            }
            m[j * 2] = lo; m[j * 2 + 1] = hi;
        }
        uint4 u;
        u.x = pkh(m[0], m[2]);   // row g,   k 2cl, 2cl+1
        u.y = pkh(m[1], m[3]);   // row g+8, k 2cl, 2cl+1
        u.z = pkh(m[4], m[6]);   // row g,   k 2cl+8, 2cl+9
        u.w = pkh(m[5], m[7]);   // row g+8, k 2cl+8, 2cl+9
        size_t unit = (size_t)band * 128 + ch * 8 + ktl;
        *(uint4*)(g_AmH + (size_t)plane * NNSZ + unit * 256 + lane * 8) = u;
    }
}

// ---------------- reduce partials, mix with fw3 -> v1 ----------------
__global__ void k_mix_v1() {
    int n = blockIdx.x * 256 + threadIdx.x;
    if (n >= N) return;
    float rs[4];
    #pragma unroll
    for (int e = 0; e < 4; e++) {
        float s = 0.f;
        #pragma unroll
        for (int ch = 0; ch < 16; ch++)
            s += g_part[(size_t)ch * (4 * N) + e * N + n];
        rs[e] = s;
    }
    #pragma unroll
    for (int c = 0; c < 4; c++)
        g_v1[c * N + n] = g_fw[2][c * 4 + 0] * rs[0] + g_fw[2][c * 4 + 1] * rs[1]
                        + g_fw[2][c * 4 + 2] * rs[2] + g_fw[2][c * 4 + 3] * rs[3];
}

// ---------------- matvec on raw A: vout_c = sum_i w[c,i] * (A_i @ vin_c) ----------------
__global__ void __launch_bounds__(256) k_matvec(const float* __restrict__ A, int stage) {
    const float* __restrict__ vin = (stage == 0) ? g_v1 : g_v2;
    float* __restrict__ vout = (stage == 0) ? g_v2 : g_v3;
    const float* wsrc = (stage == 0) ? g_fw[1] : g_fw[0];
    int n = blockIdx.x;
    int tid = threadIdx.x;
    float w[16];
    #pragma unroll
    for (int j = 0; j < 16; j++) w[j] = wsrc[j];
    float acc0 = 0.f, acc1 = 0.f, acc2 = 0.f, acc3 = 0.f;
    #pragma unroll
    for (int it = 0; it < (N / 4) / 256; it++) {
        int m4 = tid + it * 256;
        float4 vv0 = ((const float4*)(vin + 0 * N))[m4];
        float4 vv1 = ((const float4*)(vin + 1 * N))[m4];
        float4 vv2 = ((const float4*)(vin + 2 * N))[m4];
        float4 vv3 = ((const float4*)(vin + 3 * N))[m4];
        #pragma unroll
        for (int i = 0; i < 4; i++) {
            float4 a = ((const float4*)(A + (size_t)i * NNSZ + (size_t)n * N))[m4];
            float d0 = a.x * vv0.x + a.y * vv0.y + a.z * vv0.z + a.w * vv0.w;
            float d1 = a.x * vv1.x + a.y * vv1.y + a.z * vv1.z + a.w * vv1.w;
            float d2 = a.x * vv2.x + a.y * vv2.y + a.z * vv2.z + a.w * vv2.w;
            float d3 = a.x * vv3.x + a.y * vv3.y + a.z * vv3.z + a.w * vv3.w;
            acc0 = fmaf(w[0 * 4 + i], d0, acc0);
            acc1 = fmaf(w[1 * 4 + i], d1, acc1);
            acc2 = fmaf(w[2 * 4 + i], d2, acc2);
            acc3 = fmaf(w[3 * 4 + i], d3, acc3);
        }
    }
    #pragma unroll
    for (int off = 16; off > 0; off >>= 1) {
        acc0 += __shfl_down_sync(0xffffffffu, acc0, off);
        acc1 += __shfl_down_sync(0xffffffffu, acc1, off);
        acc2 += __shfl_down_sync(0xffffffffu, acc2, off);
        acc3 += __shfl_down_sync(0xffffffffu, acc3, off);
    }
    __shared__ float red[8][4];
    int lane = tid & 31, wid = tid >> 5;
    if (lane == 0) { red[wid][0] = acc0; red[wid][1] = acc1; red[wid][2] = acc2; red[wid][3] = acc3; }
    __syncthreads();
    if (tid < 4) {
        float s = 0.f;
        #pragma unroll
        for (int wv = 0; wv < 8; wv++) s += red[wv][tid];
        vout[tid * N + n] = s;
    }
}

// ---------------- d, Sp natural fp32, SpB fp16 scaled (fragment B-units) ----------------
// grid: 128 CTAs (16 nodes each = one k16 block), 256 threads
__global__ void __launch_bounds__(256) k_dSp_h() {
    __shared__ float sup[16][132];
    __shared__ float dsm[4][16];
    const int tid = threadIdx.x;
    const int k0 = blockIdx.x * 16;
    {
        int r = tid >> 4, f8 = (tid & 15) * 8;
        *(float4*)&sup[r][f8] = *(const float4*)(g_support + (size_t)(k0 + r) * F + f8);
        *(float4*)&sup[r][f8 + 4] = *(const float4*)(g_support + (size_t)(k0 + r) * F + f8 + 4);
    }
    if (tid < 64) {
        int c = tid >> 4, kk = tid & 15;
        float deg = g_v3[c * N + k0 + kk] + 1.0f;
        float d = (deg > 0.f) ? rsqrtf(deg) : 0.f;
        dsm[c][kk] = d;
        g_d[c * N + k0 + kk] = d;
    }
    __syncthreads();
    {   // natural Sp fp32
        int r = tid >> 4, f8 = (tid & 15) * 8;
        float4 s0 = *(float4*)&sup[r][f8];
        float4 s1 = *(float4*)&sup[r][f8 + 4];
        #pragma unroll
        for (int c = 0; c < 4; c++) {
            float d = dsm[c][r];
            float4 o0 = make_float4(d * s0.x, d * s0.y, d * s0.z, d * s0.w);
            float4 o1 = make_float4(d * s1.x, d * s1.y, d * s1.z, d * s1.w);
            *(float4*)(g_Sp + ((size_t)c * N + k0 + r) * F + f8) = o0;
            *(float4*)(g_Sp + ((size_t)c * N + k0 + r) * F + f8 + 4) = o1;
        }
    }
    {   // fp16 SpB B-units (scaled)
        int nt = tid >> 5, l = tid & 31;
        int g = l >> 2, cl = l & 3;
        int na = nt * 16 + g, nb = na + 8;
        int ka = 2 * cl, kb = 2 * cl + 8;
        #pragma unroll
        for (int c = 0; c < 4; c++) {
            float d0 = dsm[c][ka] * SPB_SCALE,     d1 = dsm[c][ka + 1] * SPB_SCALE;
            float d8 = dsm[c][kb] * SPB_SCALE,     d9 = dsm[c][kb + 1] * SPB_SCALE;
            uint4 u;
            u.x = pkh(d0 * sup[ka][na], d1 * sup[ka + 1][na]);
            u.y = pkh(d8 * sup[kb][na], d9 * sup[kb + 1][na]);
            u.z = pkh(d0 * sup[ka][nb], d1 * sup[ka + 1][nb]);
            u.w = pkh(d8 * sup[kb][nb], d9 * sup[kb + 1][nb]);
            *(uint4*)(g_SpBH + (size_t)c * NFSZ + ((size_t)blockIdx.x * 8 + nt) * 256 + l * 8) = u;
        }
    }
}

// ---------------- main GEMM: fp16 m16n8k16, direct-LDG, 512 threads ----------------
__global__ void __launch_bounds__(512) k_gemm_h(const float* __restrict__ bias,
                                                float* __restrict__ out, int stage) {
    __shared__ float sm[64][132];
    const int tid = threadIdx.x, lane = tid & 31, warp = tid >> 5;   // 16 warps
    const int wm = warp >> 2, wn = warp & 3;       // 4 x 4
    const int c = blockIdx.y;
    const int n0 = blockIdx.x * 64;
    const int g = lane >> 2, cl = lane & 3;

    const __half* __restrict__ Af = g_AmH + (size_t)(stage * 4 + c) * NNSZ;
    const __half* __restrict__ Bf = ((stage == 0) ? g_SpBH : (stage == 1) ? g_T0BH : g_T1BH)
                                    + (size_t)c * NFSZ;
    const uint4* __restrict__ Abase = (const uint4*)Af
        + ((size_t)(blockIdx.x * 4 + wm) * 128) * 32 + lane;
    const uint4* __restrict__ Bbase = (const uint4*)Bf + (size_t)(wn * 2) * 32 + lane;

    float acc[4][4];
    #pragma unroll
    for (int j = 0; j < 4; j++)
        #pragma unroll
        for (int q = 0; q < 4; q++) acc[j][q] = 0.f;

    uint4 ab[4], bb[4][2];
    #pragma unroll
    for (int p = 0; p < 3; p++) {
        ab[p] = Abase[(size_t)p * 32];
        bb[p][0] = Bbase[(size_t)p * 256];
        bb[p][1] = Bbase[(size_t)p * 256 + 32];
    }

    for (int kt4 = 0; kt4 < 32; kt4++) {
        #pragma unroll
        for (int s = 0; s < 4; s++) {
            const int kt = kt4 * 4 + s;
            const int slot = kt & 3;
            const int pf = kt + 3;
            if (pf < 128) {
                const int ps = pf & 3;
                ab[ps] = Abase[(size_t)pf * 32];
                bb[ps][0] = Bbase[(size_t)pf * 256];
                bb[ps][1] = Bbase[(size_t)pf * 256 + 32];
            }
            uint4 a = ab[slot];
            uint4 b0 = bb[slot][0], b1 = bb[slot][1];
            mma_f16(acc[0][0], acc[0][1], acc[0][2], acc[0][3],
                    a.x, a.y, a.z, a.w, b0.x, b0.y);
            mma_f16(acc[1][0], acc[1][1], acc[1][2], acc[1][3],
                    a.x, a.y, a.z, a.w, b0.z, b0.w);
            mma_f16(acc[2][0], acc[2][1], acc[2][2], acc[2][3],
                    a.x, a.y, a.z, a.w, b1.x, b1.y);
            mma_f16(acc[3][0], acc[3][1], acc[3][2], acc[3][3],
                    a.x, a.y, a.z, a.w, b1.z, b1.w);
        }
    }

    // park D in smem (natural [node][f])
    {
        #pragma unroll
        for (int j = 0; j < 4; j++) {
            int row = wm * 16 + g;
            int col = wn * 32 + j * 8 + 2 * cl;
            sm[row][col] = acc[j][0];
            sm[row][col + 1] = acc[j][1];
            sm[row + 8][col] = acc[j][2];
            sm[row + 8][col + 1] = acc[j][3];
        }
    }
    __syncthreads();

    if (stage < 2) {
        const float scl = (stage == 0) ? SPB_UNSCALE : 1.0f;
        __half* __restrict__ Bout = ((stage == 0) ? g_T0BH : g_T1BH) + (size_t)c * NFSZ;
        #pragma unroll
        for (int q = 0; q < 2; q++) {
            int uu = warp * 2 + q;
            int ku = uu >> 3, nu = uu & 7;
            int kb2 = ku * 16;
            int na = nu * 16 + g, nb = na + 8;
            int ka = kb2 + 2 * cl, kc = kb2 + 2 * cl + 8;
            uint4 u;
            u.x = pkh(scl * sm[ka][na],     scl * sm[ka + 1][na]);
            u.y = pkh(scl * sm[kc][na],     scl * sm[kc + 1][na]);
            u.z = pkh(scl * sm[ka][nb],     scl * sm[ka + 1][nb]);
            u.w = pkh(scl * sm[kc][nb],     scl * sm[kc + 1][nb]);
            *(uint4*)(Bout + ((size_t)(blockIdx.x * 4 + ku) * 8 + nu) * 256 + lane * 8) = u;
        }
    } else {
        const int r = tid >> 3;
        const int fc = (tid & 7) * 16;
        const int node = n0 + r;
        const float dd = g_d[c * N + node];
        const float* sp = g_Sp + ((size_t)(c * N + node)) * F;
        float* op = out + (size_t)node * (C * F) + c * F;
        #pragma unroll
        for (int j0 = 0; j0 < 16; j0 += 4) {
            float4 a4 = *(float4*)&sm[r][fc + j0];
            float4 s4 = *(const float4*)(sp + fc + j0);
            float4 b4 = *(const float4*)(bias + fc + j0);
            float4 o;
            o.x = fmaxf(dd * (a4.x + s4.x) + b4.x, 0.f);
            o.y = fmaxf(dd * (a4.y + s4.y) + b4.y, 0.f);
            o.z = fmaxf(dd * (a4.z + s4.z) + b4.z, 0.f);
            o.w = fmaxf(dd * (a4.w + s4.w) + b4.w, 0.f);
            *(float4*)(op + fc + j0) = o;
        }
    }
}

// ---------------- launcher ----------------
extern "C" void kernel_launch(void* const* d_in, const int* in_sizes, int n_in,
                              void* d_out, int out_size) {
    const float* A  = (const float*)d_in[0];   // [E,N,N]
    const float* X  = (const float*)d_in[1];   // [N,WIN]
    const float* w1 = (const float*)d_in[2];   // [C,E]
    const float* w2 = (const float*)d_in[3];   // [C,E]
    const float* w3 = (const float*)d_in[4];   // [C,C]
    const float* gw = (const float*)d_in[5];   // [WIN,F]
    const float* gb = (const float*)d_in[6];   // [F]
    float* out = (float*)d_out;                // [N, C*F]

    k_softmax<<<1, 32>>>(w1, w2, w3);
    k_premix_h<<<dim3(16, 128), 256>>>(A);       // 12 fp16 frag planes + partial rowsums
    k_support<<<N / 32, 256>>>(X, gw);           // support = X @ gcn_w
    k_mix_v1<<<N / 256, 256>>>();                // v1
    k_matvec<<<N, 256>>>(A, 0);                  // v2 = Hb @ v1
    k_matvec<<<N, 256>>>(A, 1);                  // v3 = Ha @ v2
    k_dSp_h<<<N / 16, 256>>>();                  // d, Sp fp32, SpB fp16 (x1024)
    k_gemm_h<<<dim3(N / 64, C), 512>>>(gb, out, 0);   // T0B (unscale on write)
    k_gemm_h<<<dim3(N / 64, C), 512>>>(gb, out, 1);   // T1B
    k_gemm_h<<<dim3(N / 64, C), 512>>>(gb, out, 2);   // out = relu(d*(Ha@T1+Sp)+b)
}

// round 12
// speedup vs baseline: 1.1794x; 1.1794x over previous
#include <cuda_runtime.h>
#include <cstdint>

#define N 2048
#define E 4
#define C 4
#define F 128      // W_OUT
#define WIN 256
#define NNSZ ((size_t)N * N)
#define NFSZ ((size_t)N * F)

// ---------------- scratch (static device globals; no allocation) ----------------
__device__ float g_fw[3][16];            // softmaxed weights: [0]=fw1, [1]=fw2, [2]=fw3
__device__ float g_support[N * F];       // X @ gcn_w              [n][f]
__device__ float g_part[16 * E * N];     // per-chunk partial raw rowsums
__device__ float g_v1[C * N];
__device__ float g_v2[C * N];
__device__ float g_v3[C * N];
__device__ float g_d[C * N];             // deg^-1/2
__device__ float g_Sp[C * N * F];        // diag(d)@support natural [c][n][f]
__device__ float g_SpB[C * N * F];       // fragment-order B plane (stage 0)
__device__ float g_T0B[C * N * F];       // fragment-order B plane (stage 1)
__device__ float g_T1B[C * N * F];       // fragment-order B plane (stage 2)
// fragment-ordered premixed adjacency planes: [stage*4 + c], unit = m16 x k8 (128 floats)
__device__ float g_Am[12 * NNSZ];

__device__ __forceinline__ float to_tf32(float x) {
    float r; asm("cvt.rna.tf32.f32 %0, %1;" : "=f"(r) : "f"(x)); return r;
}

__device__ __forceinline__ void mma_tf32(float& d0, float& d1, float& d2, float& d3,
                                         uint32_t a0, uint32_t a1, uint32_t a2, uint32_t a3,
                                         uint32_t b0, uint32_t b1) {
    asm volatile(
        "mma.sync.aligned.m16n8k8.row.col.f32.tf32.tf32.f32 "
        "{%0,%1,%2,%3}, {%4,%5,%6,%7}, {%8,%9}, {%0,%1,%2,%3};"
        : "+f"(d0), "+f"(d1), "+f"(d2), "+f"(d3)
        : "r"(a0), "r"(a1), "r"(a2), "r"(a3), "r"(b0), "r"(b1));
}

__device__ __forceinline__ void cp_async16(uint32_t s, const void* g) {
    asm volatile("cp.async.ca.shared.global [%0], [%1], 16;" :: "r"(s), "l"(g));
}
__device__ __forceinline__ void cp_commit() { asm volatile("cp.async.commit_group;"); }
__device__ __forceinline__ void cp_wait2() { asm volatile("cp.async.wait_group 2;"); }
__device__ __forceinline__ void cp_wait0() { asm volatile("cp.async.wait_group 0;"); }

// ---------------- tiny: softmax of 4x4 weight rows ----------------
__global__ void k_softmax(const float* __restrict__ w1,
                          const float* __restrict__ w2,
                          const float* __restrict__ w3) {
    int t = threadIdx.x;
    if (t >= 12) return;
    int mat = t >> 2, row = t & 3;
    const float* src = (mat == 0) ? w1 : (mat == 1) ? w2 : w3;
    float a0 = src[row * 4 + 0], a1 = src[row * 4 + 1];
    float a2 = src[row * 4 + 2], a3 = src[row * 4 + 3];
    float mx = fmaxf(fmaxf(a0, a1), fmaxf(a2, a3));
    float e0 = expf(a0 - mx), e1 = expf(a1 - mx), e2 = expf(a2 - mx), e3 = expf(a3 - mx);
    float inv = 1.0f / (e0 + e1 + e2 + e3);
    g_fw[mat][row * 4 + 0] = e0 * inv;
    g_fw[mat][row * 4 + 1] = e1 * inv;
    g_fw[mat][row * 4 + 2] = e2 * inv;
    g_fw[mat][row * 4 + 3] = e3 * inv;
}

// ---------------- support = X @ gcn_w ----------------
__global__ void __launch_bounds__(256) k_support(const float* __restrict__ X,
                                                 const float* __restrict__ W) {
    __shared__ float Xs[32][WIN];
    int tid = threadIdx.x;
    int row0 = blockIdx.x * 32;
    const float4* Xg = (const float4*)(X + (size_t)row0 * WIN);
    float4* Xs4 = (float4*)&Xs[0][0];
    #pragma unroll
    for (int j = 0; j < (32 * WIN / 4) / 256; j++)
        Xs4[tid + j * 256] = Xg[tid + j * 256];
    __syncthreads();
    int f = tid & 127, ty = tid >> 7;
    float acc[16];
    #pragma unroll
    for (int r = 0; r < 16; r++) acc[r] = 0.f;
    for (int k = 0; k < WIN; k++) {
        float w = W[k * F + f];
        #pragma unroll
        for (int r = 0; r < 16; r++)
            acc[r] = fmaf(Xs[ty * 16 + r][k], w, acc[r]);
    }
    #pragma unroll
    for (int r = 0; r < 16; r++)
        g_support[(size_t)(row0 + ty * 16 + r) * F + f] = acc[r];
}

// ---------------- premix: one (band, chunk) tile per CTA ----------------
__global__ void __launch_bounds__(256) k_premix_f(const float* __restrict__ A) {
    __shared__ float As[4][16][132];
    __shared__ float wsm[48];
    const int tid = threadIdx.x, lane = tid & 31, warp = tid >> 5;
    const int g = lane >> 2, cl = lane & 3;
    const int ch = blockIdx.x;
    const int band = blockIdx.y;
    const int n0 = band * 16, m0 = ch * 128;

    if (tid < 48) wsm[tid] = ((const float*)g_fw)[tid];
    #pragma unroll
    for (int e = 0; e < 4; e++)
        #pragma unroll
        for (int j = 0; j < 2; j++) {
            int idx = tid + j * 256;
            int r = idx >> 5, m4 = idx & 31;
            *(float4*)&As[e][r][m4 * 4] =
                *(const float4*)(A + (size_t)e * NNSZ + (size_t)(n0 + r) * N + m0 + m4 * 4);
        }
    __syncthreads();

    {
        int e = tid >> 6, r = (tid >> 2) & 15, part = tid & 3;
        float s = 0.f;
        #pragma unroll
        for (int i = 0; i < 32; i++) s += As[e][r][part * 32 + i];
        s += __shfl_xor_sync(0xffffffffu, s, 1);
        s += __shfl_xor_sync(0xffffffffu, s, 2);
        if (part == 0) g_part[(size_t)ch * (4 * N) + e * N + n0 + r] = s;
    }

    for (int task = warp; task < 192; task += 8) {
        int plane = task >> 4, ktl = task & 15;
        int s = plane >> 2;
        const float* wv = wsm + (2 - s) * 16 + (plane & 3) * 4;
        int col = ktl * 8 + cl;
        float v0 = 0.f, v1 = 0.f, v2 = 0.f, v3 = 0.f;
        #pragma unroll
        for (int e = 0; e < 4; e++) {
            float we = wv[e];
            v0 = fmaf(we, As[e][g][col], v0);
            v1 = fmaf(we, As[e][g + 8][col], v1);
            v2 = fmaf(we, As[e][g][col + 4], v2);
            v3 = fmaf(we, As[e][g + 8][col + 4], v3);
        }
        float4 o = make_float4(to_tf32(v0), to_tf32(v1), to_tf32(v2), to_tf32(v3));
        size_t unit = (size_t)band * 256 + ch * 16 + ktl;
        *(float4*)(g_Am + (size_t)plane * NNSZ + unit * 128 + lane * 4) = o;
    }
}

// ---------------- reduce partials, mix with fw3 -> v1 ----------------
__global__ void k_mix_v1() {
    int n = blockIdx.x * 256 + threadIdx.x;
    if (n >= N) return;
    float rs[4];
    #pragma unroll
    for (int e = 0; e < 4; e++) {
        float s = 0.f;
        #pragma unroll
        for (int ch = 0; ch < 16; ch++)
            s += g_part[(size_t)ch * (4 * N) + e * N + n];
        rs[e] = s;
    }
    #pragma unroll
    for (int c = 0; c < 4; c++)
        g_v1[c * N + n] = g_fw[2][c * 4 + 0] * rs[0] + g_fw[2][c * 4 + 1] * rs[1]
                        + g_fw[2][c * 4 + 2] * rs[2] + g_fw[2][c * 4 + 3] * rs[3];
}

// ---------------- matvec on raw A ----------------
__global__ void __launch_bounds__(256) k_matvec(const float* __restrict__ A, int stage) {
    const float* __restrict__ vin = (stage == 0) ? g_v1 : g_v2;
    float* __restrict__ vout = (stage == 0) ? g_v2 : g_v3;
    const float* wsrc = (stage == 0) ? g_fw[1] : g_fw[0];
    int n = blockIdx.x;
    int tid = threadIdx.x;
    float w[16];
    #pragma unroll
    for (int j = 0; j < 16; j++) w[j] = wsrc[j];
    float acc0 = 0.f, acc1 = 0.f, acc2 = 0.f, acc3 = 0.f;
    #pragma unroll
    for (int it = 0; it < (N / 4) / 256; it++) {
        int m4 = tid + it * 256;
        float4 vv0 = ((const float4*)(vin + 0 * N))[m4];
        float4 vv1 = ((const float4*)(vin + 1 * N))[m4];
        float4 vv2 = ((const float4*)(vin + 2 * N))[m4];
        float4 vv3 = ((const float4*)(vin + 3 * N))[m4];
        #pragma unroll
        for (int i = 0; i < 4; i++) {
            float4 a = ((const float4*)(A + (size_t)i * NNSZ + (size_t)n * N))[m4];
            float d0 = a.x * vv0.x + a.y * vv0.y + a.z * vv0.z + a.w * vv0.w;
            float d1 = a.x * vv1.x + a.y * vv1.y + a.z * vv1.z + a.w * vv1.w;
            float d2 = a.x * vv2.x + a.y * vv2.y + a.z * vv2.z + a.w * vv2.w;
            float d3 = a.x * vv3.x + a.y * vv3.y + a.z * vv3.z + a.w * vv3.w;
            acc0 = fmaf(w[0 * 4 + i], d0, acc0);
            acc1 = fmaf(w[1 * 4 + i], d1, acc1);
            acc2 = fmaf(w[2 * 4 + i], d2, acc2);
            acc3 = fmaf(w[3 * 4 + i], d3, acc3);
        }
    }
    #pragma unroll
    for (int off = 16; off > 0; off >>= 1) {
        acc0 += __shfl_down_sync(0xffffffffu, acc0, off);
        acc1 += __shfl_down_sync(0xffffffffu, acc1, off);
        acc2 += __shfl_down_sync(0xffffffffu, acc2, off);
        acc3 += __shfl_down_sync(0xffffffffu, acc3, off);
    }
    __shared__ float red[8][4];
    int lane = tid & 31, wid = tid >> 5;
    if (lane == 0) { red[wid][0] = acc0; red[wid][1] = acc1; red[wid][2] = acc2; red[wid][3] = acc3; }
    __syncthreads();
    if (tid < 4) {
        float s = 0.f;
        #pragma unroll
        for (int wv = 0; wv < 8; wv++) s += red[wv][tid];
        vout[tid * N + n] = s;
    }
}

// ---------------- d, Sp natural, SpB fragment-order ----------------
__global__ void __launch_bounds__(256) k_dSp_f() {
    __shared__ float sup[8][132];
    __shared__ float dsm[4][8];
    const int tid = threadIdx.x;
    const int k0 = blockIdx.x * 8;
    {
        int r = tid >> 5, f4 = (tid & 31) * 4;
        *(float4*)&sup[r][f4] = *(const float4*)(g_support + (size_t)(k0 + r) * F + f4);
    }
    if (tid < 32) {
        int c = tid >> 3, kk = tid & 7;
        float deg = g_v3[c * N + k0 + kk] + 1.0f;
        float d = (deg > 0.f) ? rsqrtf(deg) : 0.f;
        dsm[c][kk] = d;
        g_d[c * N + k0 + kk] = d;
    }
    __syncthreads();
    {
        int r = tid >> 5, f4 = (tid & 31) * 4;
        float4 s = *(float4*)&sup[r][f4];
        #pragma unroll
        for (int c = 0; c < 4; c++) {
            float d = dsm[c][r];
            float4 o = make_float4(d * s.x, d * s.y, d * s.z, d * s.w);
            *(float4*)(g_Sp + ((size_t)c * N + k0 + r) * F + f4) = o;
        }
    }
    {
        int nt = tid >> 5, l = tid & 31;
        int kl = l & 3, nl = nt * 16 + (l >> 2);
        #pragma unroll
        for (int c = 0; c < 4; c++) {
            float4 o;
            o.x = to_tf32(dsm[c][kl]     * sup[kl][nl]);
            o.y = to_tf32(dsm[c][kl + 4] * sup[kl + 4][nl]);
            o.z = to_tf32(dsm[c][kl]     * sup[kl][nl + 8]);
            o.w = to_tf32(dsm[c][kl + 4] * sup[kl + 4][nl + 8]);
            *(float4*)(g_SpB + (size_t)c * NFSZ + ((size_t)blockIdx.x * 8 + nt) * 128 + l * 4) = o;
        }
    }
}

// ---------------- main GEMM: cp.async pipelined (depth 4 x k32 groups), mma tf32 ----------------
// 512 threads, warp tile 16x32, grid (32, 4). Smem groups: A 4kt x 4mu x 32 uint4,
// B 4kt x 8nu x 32 uint4 -> 1536 uint4 (24 KB) per group, 4 groups = 96 KB.
#define GQ 1536                 // uint4 per group
#define GEMM_SMEM (4 * GQ * 16) // 98304 bytes

__global__ void __launch_bounds__(512) k_gemm_p(const float* __restrict__ bias,
                                                float* __restrict__ out, int stage) {
    extern __shared__ uint4 smp[];
    const int tid = threadIdx.x, lane = tid & 31, warp = tid >> 5;   // 16 warps
    const int wm = warp >> 2, wn = warp & 3;       // 4 x 4
    const int c = blockIdx.y;
    const int bx = blockIdx.x;
    const int n0 = bx * 64;

    const uint4* __restrict__ Aplane = (const uint4*)(g_Am + (size_t)(stage * 4 + c) * NNSZ);
    const uint4* __restrict__ Bplane = (const uint4*)(((stage == 0) ? g_SpB :
                                        (stage == 1) ? g_T0B : g_T1B) + (size_t)c * NFSZ);
    const uint32_t sbase = (uint32_t)__cvta_generic_to_shared(smp);

    // per-thread issue geometry
    const int ai = tid >> 7;            // m-unit 0..3
    const int aj = (tid >> 5) & 3;      // kt-in-group 0..3
    const int aln = tid & 31;

    float acc[4][4];
    #pragma unroll
    for (int j = 0; j < 4; j++)
        #pragma unroll
        for (int q = 0; q < 4; q++) acc[j][q] = 0.f;

    // prologue: groups 0..2
    #pragma unroll
    for (int p = 0; p < 3; p++) {
        const int buf = p;
        uint32_t gb = sbase + (uint32_t)(buf * GQ) * 16;
        cp_async16(gb + (uint32_t)((aj * 4 + ai) * 32 + aln) * 16,
                   Aplane + ((size_t)(bx * 4 + ai) * 256 + (size_t)(4 * p + aj)) * 32 + aln);
        #pragma unroll
        for (int q = 0; q < 2; q++) {
            int idx = tid + q * 512;
            int jb = idx >> 8, nu = (idx >> 5) & 7, lb = idx & 31;
            cp_async16(gb + (uint32_t)(512 + (jb * 8 + nu) * 32 + lb) * 16,
                       Bplane + ((size_t)(4 * p + jb) * 8 + nu) * 32 + lb);
        }
        cp_commit();
    }

    for (int g = 0; g < 64; g++) {
        cp_wait2();            // group g resident
        __syncthreads();       // all warps done with group g-1's buffer (= (g+3)&3)
        if (g + 3 < 64) {
            const int buf = (g + 3) & 3;
            uint32_t gb = sbase + (uint32_t)(buf * GQ) * 16;
            cp_async16(gb + (uint32_t)((aj * 4 + ai) * 32 + aln) * 16,
                       Aplane + ((size_t)(bx * 4 + ai) * 256 + (size_t)(4 * (g + 3) + aj)) * 32 + aln);
            #pragma unroll
            for (int q = 0; q < 2; q++) {
                int idx = tid + q * 512;
                int jb = idx >> 8, nu = (idx >> 5) & 7, lb = idx & 31;
                cp_async16(gb + (uint32_t)(512 + (jb * 8 + nu) * 32 + lb) * 16,
                           Bplane + ((size_t)(4 * (g + 3) + jb) * 8 + nu) * 32 + lb);
            }
        }
        cp_commit();

        const uint4* Ab = smp + (size_t)(g & 3) * GQ;
        const uint4* Bb = Ab + 512;
        #pragma unroll
        for (int j = 0; j < 4; j++) {
            uint4 a = Ab[(j * 4 + wm) * 32 + lane];
            uint4 b0 = Bb[(j * 8 + wn * 2) * 32 + lane];
            uint4 b1 = Bb[(j * 8 + wn * 2 + 1) * 32 + lane];
            mma_tf32(acc[0][0], acc[0][1], acc[0][2], acc[0][3],
                     a.x, a.y, a.z, a.w, b0.x, b0.y);
            mma_tf32(acc[1][0], acc[1][1], acc[1][2], acc[1][3],
                     a.x, a.y, a.z, a.w, b0.z, b0.w);
            mma_tf32(acc[2][0], acc[2][1], acc[2][2], acc[2][3],
                     a.x, a.y, a.z, a.w, b1.x, b1.y);
            mma_tf32(acc[3][0], acc[3][1], acc[3][2], acc[3][3],
                     a.x, a.y, a.z, a.w, b1.z, b1.w);
        }
    }

    cp_wait0();
    __syncthreads();

    // park D in smem (natural [node][f]) — reuse pipeline smem
    float* smf = (float*)smp;
    {
        const int g = lane >> 2, th = lane & 3;
        #pragma unroll
        for (int j = 0; j < 4; j++) {
            int row = wm * 16 + g;
            int col = wn * 32 + (j >> 1) * 16 + (j & 1) * 8 + 2 * th;
            smf[row * 132 + col] = acc[j][0];
            smf[row * 132 + col + 1] = acc[j][1];
            smf[(row + 8) * 132 + col] = acc[j][2];
            smf[(row + 8) * 132 + col + 1] = acc[j][3];
        }
    }
    __syncthreads();

    if (stage < 2) {
        float* __restrict__ Bout = ((stage == 0) ? g_T0B : g_T1B) + (size_t)c * NFSZ;
        const int ku = warp >> 1;
        const int nu0 = (warp & 1) * 4;
        const int ka = ku * 8 + (lane & 3);
        const int nloc = lane >> 2;
        #pragma unroll
        for (int q = 0; q < 4; q++) {
            int nu = nu0 + q;
            int nl = nu * 16 + nloc;
            float4 o;
            o.x = to_tf32(smf[ka * 132 + nl]);
            o.y = to_tf32(smf[(ka + 4) * 132 + nl]);
            o.z = to_tf32(smf[ka * 132 + nl + 8]);
            o.w = to_tf32(smf[(ka + 4) * 132 + nl + 8]);
            *(float4*)(Bout + ((size_t)(bx * 8 + ku) * 8 + nu) * 128 + lane * 4) = o;
        }
    } else {
        const int r = tid >> 3;
        const int fc = (tid & 7) * 16;
        const int node = n0 + r;
        const float dd = g_d[c * N + node];
        const float* sp = g_Sp + ((size_t)(c * N + node)) * F;
        float* op = out + (size_t)node * (C * F) + c * F;
        #pragma unroll
        for (int j0 = 0; j0 < 16; j0 += 4) {
            float4 a4 = *(float4*)&smf[r * 132 + fc + j0];
            float4 s4 = *(const float4*)(sp + fc + j0);
            float4 b4 = *(const float4*)(bias + fc + j0);
            float4 o;
            o.x = fmaxf(dd * (a4.x + s4.x) + b4.x, 0.f);
            o.y = fmaxf(dd * (a4.y + s4.y) + b4.y, 0.f);
            o.z = fmaxf(dd * (a4.z + s4.z) + b4.z, 0.f);
            o.w = fmaxf(dd * (a4.w + s4.w) + b4.w, 0.f);
            *(float4*)(op + fc + j0) = o;
        }
    }
}

// ---------------- launcher ----------------
extern "C" void kernel_launch(void* const* d_in, const int* in_sizes, int n_in,
                              void* d_out, int out_size) {
    const float* A  = (const float*)d_in[0];   // [E,N,N]
    const float* X  = (const float*)d_in[1];   // [N,WIN]
    const float* w1 = (const float*)d_in[2];   // [C,E]
    const float* w2 = (const float*)d_in[3];   // [C,E]
    const float* w3 = (const float*)d_in[4];   // [C,C]
    const float* gw = (const float*)d_in[5];   // [WIN,F]
    const float* gb = (const float*)d_in[6];   // [F]
    float* out = (float*)d_out;                // [N, C*F]

    static bool attr_done = false;
    if (!attr_done) {
        cudaFuncSetAttribute(k_gemm_p, cudaFuncAttributeMaxDynamicSharedMemorySize,
                             GEMM_SMEM);
        attr_done = true;
    }

    k_softmax<<<1, 32>>>(w1, w2, w3);
    k_premix_f<<<dim3(16, 128), 256>>>(A);       // 12 frag planes + partial rowsums
    k_support<<<N / 32, 256>>>(X, gw);           // support = X @ gcn_w
    k_mix_v1<<<N / 256, 256>>>();                // v1
    k_matvec<<<N, 256>>>(A, 0);                  // v2 = Hb @ v1
    k_matvec<<<N, 256>>>(A, 1);                  // v3 = Ha @ v2
    k_dSp_f<<<N / 8, 256>>>();                   // d, Sp natural, SpB frag
    k_gemm_p<<<dim3(N / 64, C), 512, GEMM_SMEM>>>(gb, out, 0);   // T0B
    k_gemm_p<<<dim3(N / 64, C), 512, GEMM_SMEM>>>(gb, out, 1);   // T1B
    k_gemm_p<<<dim3(N / 64, C), 512, GEMM_SMEM>>>(gb, out, 2);   // out
}

// round 13
// speedup vs baseline: 1.5476x; 1.3123x over previous
#include <cuda_runtime.h>
#include <cuda_fp16.h>
#include <cstdint>

#define N 2048
#define E 4
#define C 4
#define F 128      // W_OUT
#define WIN 256
#define NNSZ ((size_t)N * N)
#define NFSZ ((size_t)N * F)
#define SPB_SCALE 1024.0f
#define SPB_UNSCALE (1.0f / 1024.0f)

// ---------------- scratch (static device globals; no allocation) ----------------
__device__ float g_fw[3][16];            // softmaxed weights: [0]=fw1, [1]=fw2, [2]=fw3
__device__ float g_support[N * F];       // X @ gcn_w              [n][f]
__device__ float g_part[16 * E * N];     // per-chunk partial raw rowsums
__device__ float g_v1[C * N];
__device__ float g_v2[C * N];
__device__ float g_v3[C * N];
__device__ float g_d[C * N];             // deg^-1/2
__device__ float g_Sp[C * N * F];        // diag(d)@support natural [c][n][f] fp32
// fp16 fragment-order planes
__device__ __align__(16) __half g_SpBH[C * N * F];   // B plane stage 0 (scaled x1024)
__device__ __align__(16) __half g_T0BH[C * N * F];   // B plane stage 1 (natural)
__device__ __align__(16) __half g_T1BH[C * N * F];   // B plane stage 2 (natural)
// premixed A planes fp16: [stage*4+c], unit = m16 x k16 (256 halfs); unit idx = mt*128 + kt
__device__ __align__(16) __half g_AmH[12 * NNSZ];    // 96 MB

__device__ __forceinline__ uint32_t pkh(float a, float b) {
    __half2 h = __floats2half2_rn(a, b);
    return *(uint32_t*)&h;
}

// mma.m16n8k16 f16 -> f32 accum
__device__ __forceinline__ void mma_f16(float& d0, float& d1, float& d2, float& d3,
                                        uint32_t a0, uint32_t a1, uint32_t a2, uint32_t a3,
                                        uint32_t b0, uint32_t b1) {
    asm volatile(
        "mma.sync.aligned.m16n8k16.row.col.f32.f16.f16.f32 "
        "{%0,%1,%2,%3}, {%4,%5,%6,%7}, {%8,%9}, {%0,%1,%2,%3};"
        : "+f"(d0), "+f"(d1), "+f"(d2), "+f"(d3)
        : "r"(a0), "r"(a1), "r"(a2), "r"(a3), "r"(b0), "r"(b1));
}

__device__ __forceinline__ void cp_async16(uint32_t s, const void* g) {
    asm volatile("cp.async.ca.shared.global [%0], [%1], 16;" :: "r"(s), "l"(g));
}
__device__ __forceinline__ void cp_commit() { asm volatile("cp.async.commit_group;"); }
__device__ __forceinline__ void cp_wait2() { asm volatile("cp.async.wait_group 2;"); }
__device__ __forceinline__ void cp_wait0() { asm volatile("cp.async.wait_group 0;"); }

// ---------------- tiny: softmax of 4x4 weight rows ----------------
__global__ void k_softmax(const float* __restrict__ w1,
                          const float* __restrict__ w2,
                          const float* __restrict__ w3) {
    int t = threadIdx.x;
    if (t >= 12) return;
    int mat = t >> 2, row = t & 3;
    const float* src = (mat == 0) ? w1 : (mat == 1) ? w2 : w3;
    float a0 = src[row * 4 + 0], a1 = src[row * 4 + 1];
    float a2 = src[row * 4 + 2], a3 = src[row * 4 + 3];
    float mx = fmaxf(fmaxf(a0, a1), fmaxf(a2, a3));
    float e0 = expf(a0 - mx), e1 = expf(a1 - mx), e2 = expf(a2 - mx), e3 = expf(a3 - mx);
    float inv = 1.0f / (e0 + e1 + e2 + e3);
    g_fw[mat][row * 4 + 0] = e0 * inv;
    g_fw[mat][row * 4 + 1] = e1 * inv;
    g_fw[mat][row * 4 + 2] = e2 * inv;
    g_fw[mat][row * 4 + 3] = e3 * inv;
}

// ---------------- support = X @ gcn_w ----------------
__global__ void __launch_bounds__(256) k_support(const float* __restrict__ X,
                                                 const float* __restrict__ W) {
    __shared__ float Xs[32][WIN];
    int tid = threadIdx.x;
    int row0 = blockIdx.x * 32;
    const float4* Xg = (const float4*)(X + (size_t)row0 * WIN);
    float4* Xs4 = (float4*)&Xs[0][0];
    #pragma unroll
    for (int j = 0; j < (32 * WIN / 4) / 256; j++)
        Xs4[tid + j * 256] = Xg[tid + j * 256];
    __syncthreads();
    int f = tid & 127, ty = tid >> 7;
    float acc[16];
    #pragma unroll
    for (int r = 0; r < 16; r++) acc[r] = 0.f;
    for (int k = 0; k < WIN; k++) {
        float w = W[k * F + f];
        #pragma unroll
        for (int r = 0; r < 16; r++)
            acc[r] = fmaf(Xs[ty * 16 + r][k], w, acc[r]);
    }
    #pragma unroll
    for (int r = 0; r < 16; r++)
        g_support[(size_t)(row0 + ty * 16 + r) * F + f] = acc[r];
}

// ---------------- premix fp16: one (band, chunk) tile per CTA ----------------
// grid: (16 chunks, 128 bands), 256 threads. 12 fp16 frag planes + partial rowsums.
__global__ void __launch_bounds__(256) k_premix_h(const float* __restrict__ A) {
    __shared__ float As[4][16][132];
    __shared__ float wsm[48];
    const int tid = threadIdx.x, lane = tid & 31, warp = tid >> 5;
    const int g = lane >> 2, cl = lane & 3;
    const int ch = blockIdx.x;            // 0..15 (128-col chunk)
    const int band = blockIdx.y;          // 0..127 (16-row band)
    const int n0 = band * 16, m0 = ch * 128;

    if (tid < 48) wsm[tid] = ((const float*)g_fw)[tid];
    #pragma unroll
    for (int e = 0; e < 4; e++)
        #pragma unroll
        for (int j = 0; j < 2; j++) {
            int idx = tid + j * 256;
            int r = idx >> 5, m4 = idx & 31;
            *(float4*)&As[e][r][m4 * 4] =
                *(const float4*)(A + (size_t)e * NNSZ + (size_t)(n0 + r) * N + m0 + m4 * 4);
        }
    __syncthreads();

    // raw partial rowsums -> g_part[ch][e][n]
    {
        int e = tid >> 6, r = (tid >> 2) & 15, part = tid & 3;
        float s = 0.f;
        #pragma unroll
        for (int i = 0; i < 32; i++) s += As[e][r][part * 32 + i];
        s += __shfl_xor_sync(0xffffffffu, s, 1);
        s += __shfl_xor_sync(0xffffffffu, s, 2);
        if (part == 0) g_part[(size_t)ch * (4 * N) + e * N + n0 + r] = s;
    }

    // 12 planes x 8 k16-units = 96 warp tasks
    for (int task = warp; task < 96; task += 8) {
        int plane = task >> 3, ktl = task & 7;
        int s = plane >> 2;
        const float* wv = wsm + (2 - s) * 16 + (plane & 3) * 4;
        int cols[4] = {ktl * 16 + 2 * cl, ktl * 16 + 2 * cl + 1,
                       ktl * 16 + 2 * cl + 8, ktl * 16 + 2 * cl + 9};
        float m[8];
        #pragma unroll
        for (int j = 0; j < 4; j++) {
            float lo = 0.f, hi = 0.f;
            #pragma unroll
            for (int e = 0; e < 4; e++) {
                lo = fmaf(wv[e], As[e][g][cols[j]], lo);
                hi = fmaf(wv[e], As[e][g + 8][cols[j]], hi);
            }
            m[j * 2] = lo; m[j * 2 + 1] = hi;
        }
        uint4 u;
        u.x = pkh(m[0], m[2]);   // row g,   k 2cl, 2cl+1
        u.y = pkh(m[1], m[3]);   // row g+8, k 2cl, 2cl+1
        u.z = pkh(m[4], m[6]);   // row g,   k 2cl+8, 2cl+9
        u.w = pkh(m[5], m[7]);   // row g+8, k 2cl+8, 2cl+9
        size_t unit = (size_t)band * 128 + ch * 8 + ktl;
        *(uint4*)(g_AmH + (size_t)plane * NNSZ + unit * 256 + lane * 8) = u;
    }
}

// ---------------- reduce partials, mix with fw3 -> v1 ----------------
__global__ void k_mix_v1() {
    int n = blockIdx.x * 256 + threadIdx.x;
    if (n >= N) return;
    float rs[4];
    #pragma unroll
    for (int e = 0; e < 4; e++) {
        float s = 0.f;
        #pragma unroll
        for (int ch = 0; ch < 16; ch++)
            s += g_part[(size_t)ch * (4 * N) + e * N + n];
        rs[e] = s;
    }
    #pragma unroll
    for (int c = 0; c < 4; c++)
        g_v1[c * N + n] = g_fw[2][c * 4 + 0] * rs[0] + g_fw[2][c * 4 + 1] * rs[1]
                        + g_fw[2][c * 4 + 2] * rs[2] + g_fw[2][c * 4 + 3] * rs[3];
}

// ---------------- matvec on raw A ----------------
__global__ void __launch_bounds__(256) k_matvec(const float* __restrict__ A, int stage) {
    const float* __restrict__ vin = (stage == 0) ? g_v1 : g_v2;
    float* __restrict__ vout = (stage == 0) ? g_v2 : g_v3;
    const float* wsrc = (stage == 0) ? g_fw[1] : g_fw[0];
    int n = blockIdx.x;
    int tid = threadIdx.x;
    float w[16];
    #pragma unroll
    for (int j = 0; j < 16; j++) w[j] = wsrc[j];
    float acc0 = 0.f, acc1 = 0.f, acc2 = 0.f, acc3 = 0.f;
    #pragma unroll
    for (int it = 0; it < (N / 4) / 256; it++) {
        int m4 = tid + it * 256;
        float4 vv0 = ((const float4*)(vin + 0 * N))[m4];
        float4 vv1 = ((const float4*)(vin + 1 * N))[m4];
        float4 vv2 = ((const float4*)(vin + 2 * N))[m4];
        float4 vv3 = ((const float4*)(vin + 3 * N))[m4];
        #pragma unroll
        for (int i = 0; i < 4; i++) {
            float4 a = ((const float4*)(A + (size_t)i * NNSZ + (size_t)n * N))[m4];
            float d0 = a.x * vv0.x + a.y * vv0.y + a.z * vv0.z + a.w * vv0.w;
            float d1 = a.x * vv1.x + a.y * vv1.y + a.z * vv1.z + a.w * vv1.w;
            float d2 = a.x * vv2.x + a.y * vv2.y + a.z * vv2.z + a.w * vv2.w;
            float d3 = a.x * vv3.x + a.y * vv3.y + a.z * vv3.z + a.w * vv3.w;
            acc0 = fmaf(w[0 * 4 + i], d0, acc0);
            acc1 = fmaf(w[1 * 4 + i], d1, acc1);
            acc2 = fmaf(w[2 * 4 + i], d2, acc2);
            acc3 = fmaf(w[3 * 4 + i], d3, acc3);
        }
    }
    #pragma unroll
    for (int off = 16; off > 0; off >>= 1) {
        acc0 += __shfl_down_sync(0xffffffffu, acc0, off);
        acc1 += __shfl_down_sync(0xffffffffu, acc1, off);
        acc2 += __shfl_down_sync(0xffffffffu, acc2, off);
        acc3 += __shfl_down_sync(0xffffffffu, acc3, off);
    }
    __shared__ float red[8][4];
    int lane = tid & 31, wid = tid >> 5;
    if (lane == 0) { red[wid][0] = acc0; red[wid][1] = acc1; red[wid][2] = acc2; red[wid][3] = acc3; }
    __syncthreads();
    if (tid < 4) {
        float s = 0.f;
        #pragma unroll
        for (int wv = 0; wv < 8; wv++) s += red[wv][tid];
        vout[tid * N + n] = s;
    }
}

// ---------------- d, Sp natural fp32, SpB fp16 scaled (fragment B-units) ----------------
// grid: 128 CTAs (16 nodes each = one k16 block), 256 threads
__global__ void __launch_bounds__(256) k_dSp_h() {
    __shared__ float sup[16][132];
    __shared__ float dsm[4][16];
    const int tid = threadIdx.x;
    const int k0 = blockIdx.x * 16;
    {
        int r = tid >> 4, f8 = (tid & 15) * 8;
        *(float4*)&sup[r][f8] = *(const float4*)(g_support + (size_t)(k0 + r) * F + f8);
        *(float4*)&sup[r][f8 + 4] = *(const float4*)(g_support + (size_t)(k0 + r) * F + f8 + 4);
    }
    if (tid < 64) {
        int c = tid >> 4, kk = tid & 15;
        float deg = g_v3[c * N + k0 + kk] + 1.0f;
        float d = (deg > 0.f) ? rsqrtf(deg) : 0.f;
        dsm[c][kk] = d;
        g_d[c * N + k0 + kk] = d;
    }
    __syncthreads();
    {   // natural Sp fp32
        int r = tid >> 4, f8 = (tid & 15) * 8;
        float4 s0 = *(float4*)&sup[r][f8];
        float4 s1 = *(float4*)&sup[r][f8 + 4];
        #pragma unroll
        for (int c = 0; c < 4; c++) {
            float d = dsm[c][r];
            float4 o0 = make_float4(d * s0.x, d * s0.y, d * s0.z, d * s0.w);
            float4 o1 = make_float4(d * s1.x, d * s1.y, d * s1.z, d * s1.w);
            *(float4*)(g_Sp + ((size_t)c * N + k0 + r) * F + f8) = o0;
            *(float4*)(g_Sp + ((size_t)c * N + k0 + r) * F + f8 + 4) = o1;
        }
    }
    {   // fp16 SpB B-units (scaled x1024)
        int nt = tid >> 5, l = tid & 31;
        int g = l >> 2, cl = l & 3;
        int na = nt * 16 + g, nb = na + 8;
        int ka = 2 * cl, kb = 2 * cl + 8;
        #pragma unroll
        for (int c = 0; c < 4; c++) {
            float d0 = dsm[c][ka] * SPB_SCALE,     d1 = dsm[c][ka + 1] * SPB_SCALE;
            float d8 = dsm[c][kb] * SPB_SCALE,     d9 = dsm[c][kb + 1] * SPB_SCALE;
            uint4 u;
            u.x = pkh(d0 * sup[ka][na], d1 * sup[ka + 1][na]);
            u.y = pkh(d8 * sup[kb][na], d9 * sup[kb + 1][na]);
            u.z = pkh(d0 * sup[ka][nb], d1 * sup[ka + 1][nb]);
            u.w = pkh(d8 * sup[kb][nb], d9 * sup[kb + 1][nb]);
            *(uint4*)(g_SpBH + (size_t)c * NFSZ + ((size_t)blockIdx.x * 8 + nt) * 256 + l * 8) = u;
        }
    }
}

// ---------------- main GEMM: fp16 m16n8k16, cp.async pipelined (depth 4 x k64 groups) ----------------
// 512 threads, warp tile 16x32, grid (32, 4). Group = 4 kt16 x (4 m-units + 8 n-units) x 32 uint4
// = 1536 uint4 (24 KB); 4 groups = 96 KB. 32 groups total (K=2048 / 64).
#define GQ 1536
#define GEMM_SMEM (4 * GQ * 16)

__global__ void __launch_bounds__(512) k_gemm_hp(const float* __restrict__ bias,
                                                 float* __restrict__ out, int stage) {
    extern __shared__ uint4 smp[];
    const int tid = threadIdx.x, lane = tid & 31, warp = tid >> 5;   // 16 warps
    const int wm = warp >> 2, wn = warp & 3;       // 4 x 4
    const int c = blockIdx.y;
    const int bx = blockIdx.x;
    const int n0 = bx * 64;
    const int g = lane >> 2, cl = lane & 3;

    const uint4* __restrict__ Aplane = (const uint4*)(g_AmH + (size_t)(stage * 4 + c) * NNSZ);
    const uint4* __restrict__ Bplane = (const uint4*)(((stage == 0) ? g_SpBH :
                                        (stage == 1) ? g_T0BH : g_T1BH) + (size_t)c * NFSZ);
    const uint32_t sbase = (uint32_t)__cvta_generic_to_shared(smp);

    // per-thread cp.async issue geometry
    const int ai = tid >> 7;            // m-unit 0..3
    const int aj = (tid >> 5) & 3;      // kt-in-group 0..3
    const int aln = tid & 31;

    float acc[4][4];
    #pragma unroll
    for (int j = 0; j < 4; j++)
        #pragma unroll
        for (int q = 0; q < 4; q++) acc[j][q] = 0.f;

    // prologue: groups 0..2
    #pragma unroll
    for (int p = 0; p < 3; p++) {
        uint32_t gb = sbase + (uint32_t)(p * GQ) * 16;
        cp_async16(gb + (uint32_t)((aj * 4 + ai) * 32 + aln) * 16,
                   Aplane + ((size_t)(bx * 4 + ai) * 128 + (size_t)(4 * p + aj)) * 32 + aln);
        #pragma unroll
        for (int q = 0; q < 2; q++) {
            int idx = tid + q * 512;
            int jb = idx >> 8, nu = (idx >> 5) & 7, lb = idx & 31;
            cp_async16(gb + (uint32_t)(512 + (jb * 8 + nu) * 32 + lb) * 16,
                       Bplane + ((size_t)(4 * p + jb) * 8 + nu) * 32 + lb);
        }
        cp_commit();
    }

    for (int gr = 0; gr < 32; gr++) {
        cp_wait2();
        __syncthreads();
        if (gr + 3 < 32) {
            const int buf = (gr + 3) & 3;
            uint32_t gb = sbase + (uint32_t)(buf * GQ) * 16;
            cp_async16(gb + (uint32_t)((aj * 4 + ai) * 32 + aln) * 16,
                       Aplane + ((size_t)(bx * 4 + ai) * 128 + (size_t)(4 * (gr + 3) + aj)) * 32 + aln);
            #pragma unroll
            for (int q = 0; q < 2; q++) {
                int idx = tid + q * 512;
                int jb = idx >> 8, nu = (idx >> 5) & 7, lb = idx & 31;
                cp_async16(gb + (uint32_t)(512 + (jb * 8 + nu) * 32 + lb) * 16,
                           Bplane + ((size_t)(4 * (gr + 3) + jb) * 8 + nu) * 32 + lb);
            }
        }
        cp_commit();

        const uint4* Ab = smp + (size_t)(gr & 3) * GQ;
        const uint4* Bb = Ab + 512;
        #pragma unroll
        for (int j = 0; j < 4; j++) {
            uint4 a = Ab[(j * 4 + wm) * 32 + lane];
            uint4 b0 = Bb[(j * 8 + wn * 2) * 32 + lane];
            uint4 b1 = Bb[(j * 8 + wn * 2 + 1) * 32 + lane];
            mma_f16(acc[0][0], acc[0][1], acc[0][2], acc[0][3],
                    a.x, a.y, a.z, a.w, b0.x, b0.y);
            mma_f16(acc[1][0], acc[1][1], acc[1][2], acc[1][3],
                    a.x, a.y, a.z, a.w, b0.z, b0.w);
            mma_f16(acc[2][0], acc[2][1], acc[2][2], acc[2][3],
                    a.x, a.y, a.z, a.w, b1.x, b1.y);
            mma_f16(acc[3][0], acc[3][1], acc[3][2], acc[3][3],
                    a.x, a.y, a.z, a.w, b1.z, b1.w);
        }
    }

    cp_wait0();
    __syncthreads();

    // park D in smem (natural [node][f]) — reuse pipeline smem
    float* smf = (float*)smp;
    {
        #pragma unroll
        for (int j = 0; j < 4; j++) {
            int row = wm * 16 + g;
            int col = wn * 32 + j * 8 + 2 * cl;
            smf[row * 132 + col] = acc[j][0];
            smf[row * 132 + col + 1] = acc[j][1];
            smf[(row + 8) * 132 + col] = acc[j][2];
            smf[(row + 8) * 132 + col + 1] = acc[j][3];
        }
    }
    __syncthreads();

    if (stage < 2) {
        const float scl = (stage == 0) ? SPB_UNSCALE : 1.0f;
        __half* __restrict__ Bout = ((stage == 0) ? g_T0BH : g_T1BH) + (size_t)c * NFSZ;
        #pragma unroll
        for (int q = 0; q < 2; q++) {
            int uu = warp * 2 + q;
            int ku = uu >> 3, nu = uu & 7;
            int kb2 = ku * 16;
            int na = nu * 16 + g, nb = na + 8;
            int ka = kb2 + 2 * cl, kc = kb2 + 2 * cl + 8;
            uint4 u;
            u.x = pkh(scl * smf[ka * 132 + na],     scl * smf[(ka + 1) * 132 + na]);
            u.y = pkh(scl * smf[kc * 132 + na],     scl * smf[(kc + 1) * 132 + na]);
            u.z = pkh(scl * smf[ka * 132 + nb],     scl * smf[(ka + 1) * 132 + nb]);
            u.w = pkh(scl * smf[kc * 132 + nb],     scl * smf[(kc + 1) * 132 + nb]);
            *(uint4*)(Bout + ((size_t)(bx * 4 + ku) * 8 + nu) * 256 + lane * 8) = u;
        }
    } else {
        const int r = tid >> 3;
        const int fc = (tid & 7) * 16;
        const int node = n0 + r;
        const float dd = g_d[c * N + node];
        const float* sp = g_Sp + ((size_t)(c * N + node)) * F;
        float* op = out + (size_t)node * (C * F) + c * F;
        #pragma unroll
        for (int j0 = 0; j0 < 16; j0 += 4) {
            float4 a4 = *(float4*)&smf[r * 132 + fc + j0];
            float4 s4 = *(const float4*)(sp + fc + j0);
            float4 b4 = *(const float4*)(bias + fc + j0);
            float4 o;
            o.x = fmaxf(dd * (a4.x + s4.x) + b4.x, 0.f);
            o.y = fmaxf(dd * (a4.y + s4.y) + b4.y, 0.f);
            o.z = fmaxf(dd * (a4.z + s4.z) + b4.z, 0.f);
            o.w = fmaxf(dd * (a4.w + s4.w) + b4.w, 0.f);
            *(float4*)(op + fc + j0) = o;
        }
    }
}

// ---------------- launcher ----------------
extern "C" void kernel_launch(void* const* d_in, const int* in_sizes, int n_in,
                              void* d_out, int out_size) {
    const float* A  = (const float*)d_in[0];   // [E,N,N]
    const float* X  = (const float*)d_in[1];   // [N,WIN]
    const float* w1 = (const float*)d_in[2];   // [C,E]
    const float* w2 = (const float*)d_in[3];   // [C,E]
    const float* w3 = (const float*)d_in[4];   // [C,C]
    const float* gw = (const float*)d_in[5];   // [WIN,F]
    const float* gb = (const float*)d_in[6];   // [F]
    float* out = (float*)d_out;                // [N, C*F]

    static bool attr_done = false;
    if (!attr_done) {
        cudaFuncSetAttribute(k_gemm_hp, cudaFuncAttributeMaxDynamicSharedMemorySize,
                             GEMM_SMEM);
        attr_done = true;
    }

    k_softmax<<<1, 32>>>(w1, w2, w3);
    k_premix_h<<<dim3(16, 128), 256>>>(A);       // 12 fp16 frag planes + partial rowsums
    k_support<<<N / 32, 256>>>(X, gw);           // support = X @ gcn_w
    k_mix_v1<<<N / 256, 256>>>();                // v1
    k_matvec<<<N, 256>>>(A, 0);                  // v2 = Hb @ v1
    k_matvec<<<N, 256>>>(A, 1);                  // v3 = Ha @ v2
    k_dSp_h<<<N / 16, 256>>>();                  // d, Sp fp32, SpB fp16 (x1024)
    k_gemm_hp<<<dim3(N / 64, C), 512, GEMM_SMEM>>>(gb, out, 0);   // T0B (unscale on write)
    k_gemm_hp<<<dim3(N / 64, C), 512, GEMM_SMEM>>>(gb, out, 1);   // T1B
    k_gemm_hp<<<dim3(N / 64, C), 512, GEMM_SMEM>>>(gb, out, 2);   // out
}

// round 14
// speedup vs baseline: 1.7164x; 1.1091x over previous
#include <cuda_runtime.h>
#include <cuda_fp16.h>
#include <cstdint>

#define N 2048
#define E 4
#define C 4
#define F 128      // W_OUT
#define WIN 256
#define NNSZ ((size_t)N * N)
#define NFSZ ((size_t)N * F)
#define SPB_SCALE 1024.0f
#define SPB_UNSCALE (1.0f / 1024.0f)

// ---------------- scratch (static device globals; no allocation) ----------------
__device__ float g_fw[3][16];            // softmaxed weights: [0]=fw1, [1]=fw2, [2]=fw3
__device__ float g_support[N * F];       // X @ gcn_w              [n][f]
__device__ float g_part[16 * E * N];     // per-chunk partial raw rowsums
__device__ float g_v1[C * N];
__device__ float g_v2p[4][C * N];        // split-k partials of v2
__device__ float g_v3p[4][C * N];        // split-k partials of v3
__device__ float g_d[C * N];             // deg^-1/2
__device__ float g_Sp[C * N * F];        // diag(d)@support natural [c][n][f] fp32
// fp16 fragment-order planes
__device__ __align__(16) __half g_SpBH[C * N * F];   // B plane stage 0 (scaled x1024)
__device__ __align__(16) __half g_T0BH[C * N * F];   // B plane stage 1 (natural)
__device__ __align__(16) __half g_T1BH[C * N * F];   // B plane stage 2 (natural)
// premixed A planes fp16: [stage*4+c], unit = m16 x k16 (256 halfs); unit idx = mt*128 + kt
__device__ __align__(16) __half g_AmH[12 * NNSZ];    // 96 MB

__device__ __forceinline__ uint32_t pkh(float a, float b) {
    __half2 h = __floats2half2_rn(a, b);
    return *(uint32_t*)&h;
}

// mma.m16n8k16 f16 -> f32 accum
__device__ __forceinline__ void mma_f16(float& d0, float& d1, float& d2, float& d3,
                                        uint32_t a0, uint32_t a1, uint32_t a2, uint32_t a3,
                                        uint32_t b0, uint32_t b1) {
    asm volatile(
        "mma.sync.aligned.m16n8k16.row.col.f32.f16.f16.f32 "
        "{%0,%1,%2,%3}, {%4,%5,%6,%7}, {%8,%9}, {%0,%1,%2,%3};"
        : "+f"(d0), "+f"(d1), "+f"(d2), "+f"(d3)
        : "r"(a0), "r"(a1), "r"(a2), "r"(a3), "r"(b0), "r"(b1));
}

__device__ __forceinline__ void cp_async16(uint32_t s, const void* g) {
    asm volatile("cp.async.ca.shared.global [%0], [%1], 16;" :: "r"(s), "l"(g));
}
__device__ __forceinline__ void cp_commit() { asm volatile("cp.async.commit_group;"); }
__device__ __forceinline__ void cp_wait2() { asm volatile("cp.async.wait_group 2;"); }
__device__ __forceinline__ void cp_wait0() { asm volatile("cp.async.wait_group 0;"); }

// ---------------- tiny: softmax of 4x4 weight rows ----------------
__global__ void k_softmax(const float* __restrict__ w1,
                          const float* __restrict__ w2,
                          const float* __restrict__ w3) {
    int t = threadIdx.x;
    if (t >= 12) return;
    int mat = t >> 2, row = t & 3;
    const float* src = (mat == 0) ? w1 : (mat == 1) ? w2 : w3;
    float a0 = src[row * 4 + 0], a1 = src[row * 4 + 1];
    float a2 = src[row * 4 + 2], a3 = src[row * 4 + 3];
    float mx = fmaxf(fmaxf(a0, a1), fmaxf(a2, a3));
    float e0 = expf(a0 - mx), e1 = expf(a1 - mx), e2 = expf(a2 - mx), e3 = expf(a3 - mx);
    float inv = 1.0f / (e0 + e1 + e2 + e3);
    g_fw[mat][row * 4 + 0] = e0 * inv;
    g_fw[mat][row * 4 + 1] = e1 * inv;
    g_fw[mat][row * 4 + 2] = e2 * inv;
    g_fw[mat][row * 4 + 3] = e3 * inv;
}

// ---------------- support = X @ gcn_w  (+ fused mix_v1 tail) ----------------
__global__ void __launch_bounds__(256) k_support(const float* __restrict__ X,
                                                 const float* __restrict__ W) {
    __shared__ float Xs[32][WIN];
    __shared__ float rsum[32][4];
    int tid = threadIdx.x;
    int row0 = blockIdx.x * 32;
    const float4* Xg = (const float4*)(X + (size_t)row0 * WIN);
    float4* Xs4 = (float4*)&Xs[0][0];
    #pragma unroll
    for (int j = 0; j < (32 * WIN / 4) / 256; j++)
        Xs4[tid + j * 256] = Xg[tid + j * 256];

    // fused mix_v1 part A: reduce g_part for this CTA's 32 rows
    if (tid < 128) {
        int r = tid >> 2, e = tid & 3;
        float s = 0.f;
        #pragma unroll
        for (int ch = 0; ch < 16; ch++)
            s += g_part[(size_t)ch * (4 * N) + e * N + row0 + r];
        rsum[r][e] = s;
    }
    __syncthreads();
    if (tid < 32) {
        int r = tid;
        #pragma unroll
        for (int c = 0; c < 4; c++)
            g_v1[c * N + row0 + r] =
                g_fw[2][c * 4 + 0] * rsum[r][0] + g_fw[2][c * 4 + 1] * rsum[r][1]
              + g_fw[2][c * 4 + 2] * rsum[r][2] + g_fw[2][c * 4 + 3] * rsum[r][3];
    }

    int f = tid & 127, ty = tid >> 7;
    float acc[16];
    #pragma unroll
    for (int r = 0; r < 16; r++) acc[r] = 0.f;
    for (int k = 0; k < WIN; k++) {
        float w = W[k * F + f];
        #pragma unroll
        for (int r = 0; r < 16; r++)
            acc[r] = fmaf(Xs[ty * 16 + r][k], w, acc[r]);
    }
    #pragma unroll
    for (int r = 0; r < 16; r++)
        g_support[(size_t)(row0 + ty * 16 + r) * F + f] = acc[r];
}

// ---------------- premix fp16: one (band, chunk) tile per CTA ----------------
// grid: (16 chunks, 128 bands), 256 threads. 12 fp16 frag planes + partial rowsums.
__global__ void __launch_bounds__(256) k_premix_h(const float* __restrict__ A) {
    __shared__ float As[4][16][132];
    __shared__ float wsm[48];
    const int tid = threadIdx.x, lane = tid & 31, warp = tid >> 5;
    const int g = lane >> 2, cl = lane & 3;
    const int ch = blockIdx.x;            // 0..15 (128-col chunk)
    const int band = blockIdx.y;          // 0..127 (16-row band)
    const int n0 = band * 16, m0 = ch * 128;

    if (tid < 48) wsm[tid] = ((const float*)g_fw)[tid];
    #pragma unroll
    for (int e = 0; e < 4; e++)
        #pragma unroll
        for (int j = 0; j < 2; j++) {
            int idx = tid + j * 256;
            int r = idx >> 5, m4 = idx & 31;
            *(float4*)&As[e][r][m4 * 4] =
                *(const float4*)(A + (size_t)e * NNSZ + (size_t)(n0 + r) * N + m0 + m4 * 4);
        }
    __syncthreads();

    // raw partial rowsums -> g_part[ch][e][n]
    {
        int e = tid >> 6, r = (tid >> 2) & 15, part = tid & 3;
        float s = 0.f;
        #pragma unroll
        for (int i = 0; i < 32; i++) s += As[e][r][part * 32 + i];
        s += __shfl_xor_sync(0xffffffffu, s, 1);
        s += __shfl_xor_sync(0xffffffffu, s, 2);
        if (part == 0) g_part[(size_t)ch * (4 * N) + e * N + n0 + r] = s;
    }

    // 12 planes x 8 k16-units = 96 warp tasks
    for (int task = warp; task < 96; task += 8) {
        int plane = task >> 3, ktl = task & 7;
        int s = plane >> 2;
        const float* wv = wsm + (2 - s) * 16 + (plane & 3) * 4;
        int cols[4] = {ktl * 16 + 2 * cl, ktl * 16 + 2 * cl + 1,
                       ktl * 16 + 2 * cl + 8, ktl * 16 + 2 * cl + 9};
        float m[8];
        #pragma unroll
        for (int j = 0; j < 4; j++) {
            float lo = 0.f, hi = 0.f;
            #pragma unroll
            for (int e = 0; e < 4; e++) {
                lo = fmaf(wv[e], As[e][g][cols[j]], lo);
                hi = fmaf(wv[e], As[e][g + 8][cols[j]], hi);
            }
            m[j * 2] = lo; m[j * 2 + 1] = hi;
        }
        uint4 u;
        u.x = pkh(m[0], m[2]);
        u.y = pkh(m[1], m[3]);
        u.z = pkh(m[4], m[6]);
        u.w = pkh(m[5], m[7]);
        size_t unit = (size_t)band * 128 + ch * 8 + ktl;
        *(uint4*)(g_AmH + (size_t)plane * NNSZ + unit * 256 + lane * 8) = u;
    }
}

// ---------------- matvec on fp16 premixed planes, split-k ----------------
// grid (128 bands, 4 ksplit), 256 threads. stage0: planes 4..7 (fw2), vin=v1 -> g_v2p
//                                           stage1: planes 8..11 (fw1), vin=Σ g_v2p -> g_v3p
__global__ void __launch_bounds__(256) k_matvec_h(int stage) {
    __shared__ float vs[4][512];      // vin slice, 4 channels x 512 m (8 KB)
    __shared__ float red[8][16][4];
    const int tid = threadIdx.x, lane = tid & 31, warp = tid >> 5;
    const int band = blockIdx.x, ks = blockIdx.y;
    const int g = lane >> 2, cl = lane & 3;

    // load vin slice [ks*512, ks*512+512)
    if (stage == 0) {
        #pragma unroll
        for (int i = 0; i < 2; i++) {
            int idx = tid + i * 256;                 // 0..511 over (c, m/ pack of 4)
            int c = idx >> 7, m4 = (idx & 127) * 4;
            *(float4*)&vs[c][m4] = *(const float4*)(g_v1 + c * N + ks * 512 + m4);
        }
    } else {
        #pragma unroll
        for (int i = 0; i < 2; i++) {
            int idx = tid + i * 256;
            int c = idx >> 7, m4 = (idx & 127) * 4;
            float4 s = *(const float4*)(g_v2p[0] + c * N + ks * 512 + m4);
            #pragma unroll
            for (int p = 1; p < 4; p++) {
                float4 t = *(const float4*)(g_v2p[p] + c * N + ks * 512 + m4);
                s.x += t.x; s.y += t.y; s.z += t.z; s.w += t.w;
            }
            *(float4*)&vs[c][m4] = s;
        }
    }
    __syncthreads();

    const uint4* __restrict__ P = (const uint4*)(g_AmH + (size_t)(stage + 1) * 4 * NNSZ);
    const size_t PST = NNSZ / 8;      // uint4 stride between channel planes

    float acc0[4] = {0.f, 0.f, 0.f, 0.f};   // row g
    float acc1[4] = {0.f, 0.f, 0.f, 0.f};   // row g+8
    #pragma unroll
    for (int j = 0; j < 4; j++) {
        int ktl = warp * 4 + j;                  // 0..31 local kt
        size_t bi = ((size_t)band * 128 + ks * 32 + ktl) * 32 + lane;
        int mL = ktl * 16 + 2 * cl;
        float v0 = vs[0][mL], v0b = vs[0][mL + 1], v0c = vs[0][mL + 8], v0d = vs[0][mL + 9];
        #pragma unroll
        for (int c = 0; c < 4; c++) {
            uint4 u = P[bi + (size_t)c * PST];
            float vx = vs[c][mL], vy = vs[c][mL + 1];
            float vz = vs[c][mL + 8], vw = vs[c][mL + 9];
            float2 hx = __half22float2(*(__half2*)&u.x);
            float2 hy = __half22float2(*(__half2*)&u.y);
            float2 hz = __half22float2(*(__half2*)&u.z);
            float2 hw = __half22float2(*(__half2*)&u.w);
            acc0[c] = fmaf(hx.x, vx, fmaf(hx.y, vy, fmaf(hz.x, vz, fmaf(hz.y, vw, acc0[c]))));
            acc1[c] = fmaf(hy.x, vx, fmaf(hy.y, vy, fmaf(hw.x, vz, fmaf(hw.y, vw, acc1[c]))));
        }
        (void)v0; (void)v0b; (void)v0c; (void)v0d;
    }
    #pragma unroll
    for (int d = 1; d <= 2; d <<= 1)
        #pragma unroll
        for (int c = 0; c < 4; c++) {
            acc0[c] += __shfl_xor_sync(0xffffffffu, acc0[c], d);
            acc1[c] += __shfl_xor_sync(0xffffffffu, acc1[c], d);
        }
    if (cl == 0) {
        #pragma unroll
        for (int c = 0; c < 4; c++) {
            red[warp][g][c] = acc0[c];
            red[warp][g + 8][c] = acc1[c];
        }
    }
    __syncthreads();
    float* vout = (stage == 0) ? g_v2p[ks] : g_v3p[ks];
    if (tid < 64) {
        int row = tid >> 2, c = tid & 3;
        float s = 0.f;
        #pragma unroll
        for (int wv = 0; wv < 8; wv++) s += red[wv][row][c];
        vout[c * N + band * 16 + row] = s;
    }
}

// ---------------- d, Sp natural fp32, SpB fp16 scaled (fragment B-units) ----------------
// grid: 128 CTAs (16 nodes each = one k16 block), 256 threads
__global__ void __launch_bounds__(256) k_dSp_h() {
    __shared__ float sup[16][132];
    __shared__ float dsm[4][16];
    const int tid = threadIdx.x;
    const int k0 = blockIdx.x * 16;
    {
        int r = tid >> 4, f8 = (tid & 15) * 8;
        *(float4*)&sup[r][f8] = *(const float4*)(g_support + (size_t)(k0 + r) * F + f8);
        *(float4*)&sup[r][f8 + 4] = *(const float4*)(g_support + (size_t)(k0 + r) * F + f8 + 4);
    }
    if (tid < 64) {
        int c = tid >> 4, kk = tid & 15;
        float v3 = g_v3p[0][c * N + k0 + kk] + g_v3p[1][c * N + k0 + kk]
                 + g_v3p[2][c * N + k0 + kk] + g_v3p[3][c * N + k0 + kk];
        float deg = v3 + 1.0f;
        float d = (deg > 0.f) ? rsqrtf(deg) : 0.f;
        dsm[c][kk] = d;
        g_d[c * N + k0 + kk] = d;
    }
    __syncthreads();
    {   // natural Sp fp32
        int r = tid >> 4, f8 = (tid & 15) * 8;
        float4 s0 = *(float4*)&sup[r][f8];
        float4 s1 = *(float4*)&sup[r][f8 + 4];
        #pragma unroll
        for (int c = 0; c < 4; c++) {
            float d = dsm[c][r];
            float4 o0 = make_float4(d * s0.x, d * s0.y, d * s0.z, d * s0.w);
            float4 o1 = make_float4(d * s1.x, d * s1.y, d * s1.z, d * s1.w);
            *(float4*)(g_Sp + ((size_t)c * N + k0 + r) * F + f8) = o0;
            *(float4*)(g_Sp + ((size_t)c * N + k0 + r) * F + f8 + 4) = o1;
        }
    }
    {   // fp16 SpB B-units (scaled x1024)
        int nt = tid >> 5, l = tid & 31;
        int g = l >> 2, cl = l & 3;
        int na = nt * 16 + g, nb = na + 8;
        int ka = 2 * cl, kb = 2 * cl + 8;
        #pragma unroll
        for (int c = 0; c < 4; c++) {
            float d0 = dsm[c][ka] * SPB_SCALE,     d1 = dsm[c][ka + 1] * SPB_SCALE;
            float d8 = dsm[c][kb] * SPB_SCALE,     d9 = dsm[c][kb + 1] * SPB_SCALE;
            uint4 u;
            u.x = pkh(d0 * sup[ka][na], d1 * sup[ka + 1][na]);
            u.y = pkh(d8 * sup[kb][na], d9 * sup[kb + 1][na]);
            u.z = pkh(d0 * sup[ka][nb], d1 * sup[ka + 1][nb]);
            u.w = pkh(d8 * sup[kb][nb], d9 * sup[kb + 1][nb]);
            *(uint4*)(g_SpBH + (size_t)c * NFSZ + ((size_t)blockIdx.x * 8 + nt) * 256 + l * 8) = u;
        }
    }
}

// ---------------- main GEMM: fp16 m16n8k16, cp.async pipelined (depth 4 x k64 groups) ----------------
#define GQ 1536
#define GEMM_SMEM (4 * GQ * 16)

__global__ void __launch_bounds__(512) k_gemm_hp(const float* __restrict__ bias,
                                                 float* __restrict__ out, int stage) {
    extern __shared__ uint4 smp[];
    const int tid = threadIdx.x, lane = tid & 31, warp = tid >> 5;   // 16 warps
    const int wm = warp >> 2, wn = warp & 3;       // 4 x 4
    const int c = blockIdx.y;
    const int bx = blockIdx.x;
    const int n0 = bx * 64;
    const int g = lane >> 2, cl = lane & 3;

    const uint4* __restrict__ Aplane = (const uint4*)(g_AmH + (size_t)(stage * 4 + c) * NNSZ);
    const uint4* __restrict__ Bplane = (const uint4*)(((stage == 0) ? g_SpBH :
                                        (stage == 1) ? g_T0BH : g_T1BH) + (size_t)c * NFSZ);
    const uint32_t sbase = (uint32_t)__cvta_generic_to_shared(smp);

    const int ai = tid >> 7;
    const int aj = (tid >> 5) & 3;
    const int aln = tid & 31;

    float acc[4][4];
    #pragma unroll
    for (int j = 0; j < 4; j++)
        #pragma unroll
        for (int q = 0; q < 4; q++) acc[j][q] = 0.f;

    #pragma unroll
    for (int p = 0; p < 3; p++) {
        uint32_t gb = sbase + (uint32_t)(p * GQ) * 16;
        cp_async16(gb + (uint32_t)((aj * 4 + ai) * 32 + aln) * 16,
                   Aplane + ((size_t)(bx * 4 + ai) * 128 + (size_t)(4 * p + aj)) * 32 + aln);
        #pragma unroll
        for (int q = 0; q < 2; q++) {
            int idx = tid + q * 512;
            int jb = idx >> 8, nu = (idx >> 5) & 7, lb = idx & 31;
            cp_async16(gb + (uint32_t)(512 + (jb * 8 + nu) * 32 + lb) * 16,
                       Bplane + ((size_t)(4 * p + jb) * 8 + nu) * 32 + lb);
        }
        cp_commit();
    }

    for (int gr = 0; gr < 32; gr++) {
        cp_wait2();
        __syncthreads();
        if (gr + 3 < 32) {
            const int buf = (gr + 3) & 3;
            uint32_t gb = sbase + (uint32_t)(buf * GQ) * 16;
            cp_async16(gb + (uint32_t)((aj * 4 + ai) * 32 + aln) * 16,
                       Aplane + ((size_t)(bx * 4 + ai) * 128 + (size_t)(4 * (gr + 3) + aj)) * 32 + aln);
            #pragma unroll
            for (int q = 0; q < 2; q++) {
                int idx = tid + q * 512;
                int jb = idx >> 8, nu = (idx >> 5) & 7, lb = idx & 31;
                cp_async16(gb + (uint32_t)(512 + (jb * 8 + nu) * 32 + lb) * 16,
                           Bplane + ((size_t)(4 * (gr + 3) + jb) * 8 + nu) * 32 + lb);
            }
        }
        cp_commit();

        const uint4* Ab = smp + (size_t)(gr & 3) * GQ;
        const uint4* Bb = Ab + 512;
        #pragma unroll
        for (int j = 0; j < 4; j++) {
            uint4 a = Ab[(j * 4 + wm) * 32 + lane];
            uint4 b0 = Bb[(j * 8 + wn * 2) * 32 + lane];
            uint4 b1 = Bb[(j * 8 + wn * 2 + 1) * 32 + lane];
            mma_f16(acc[0][0], acc[0][1], acc[0][2], acc[0][3],
                    a.x, a.y, a.z, a.w, b0.x, b0.y);
            mma_f16(acc[1][0], acc[1][1], acc[1][2], acc[1][3],
                    a.x, a.y, a.z, a.w, b0.z, b0.w);
            mma_f16(acc[2][0], acc[2][1], acc[2][2], acc[2][3],
                    a.x, a.y, a.z, a.w, b1.x, b1.y);
            mma_f16(acc[3][0], acc[3][1], acc[3][2], acc[3][3],
                    a.x, a.y, a.z, a.w, b1.z, b1.w);
        }
    }

    cp_wait0();
    __syncthreads();

    float* smf = (float*)smp;
    {
        #pragma unroll
        for (int j = 0; j < 4; j++) {
            int row = wm * 16 + g;
            int col = wn * 32 + j * 8 + 2 * cl;
            smf[row * 132 + col] = acc[j][0];
            smf[row * 132 + col + 1] = acc[j][1];
            smf[(row + 8) * 132 + col] = acc[j][2];
            smf[(row + 8) * 132 + col + 1] = acc[j][3];
        }
    }
    __syncthreads();

    if (stage < 2) {
        const float scl = (stage == 0) ? SPB_UNSCALE : 1.0f;
        __half* __restrict__ Bout = ((stage == 0) ? g_T0BH : g_T1BH) + (size_t)c * NFSZ;
        #pragma unroll
        for (int q = 0; q < 2; q++) {
            int uu = warp * 2 + q;
            int ku = uu >> 3, nu = uu & 7;
            int kb2 = ku * 16;
            int na = nu * 16 + g, nb = na + 8;
            int ka = kb2 + 2 * cl, kc = kb2 + 2 * cl + 8;
            uint4 u;
            u.x = pkh(scl * smf[ka * 132 + na],     scl * smf[(ka + 1) * 132 + na]);
            u.y = pkh(scl * smf[kc * 132 + na],     scl * smf[(kc + 1) * 132 + na]);
            u.z = pkh(scl * smf[ka * 132 + nb],     scl * smf[(ka + 1) * 132 + nb]);
            u.w = pkh(scl * smf[kc * 132 + nb],     scl * smf[(kc + 1) * 132 + nb]);
            *(uint4*)(Bout + ((size_t)(bx * 4 + ku) * 8 + nu) * 256 + lane * 8) = u;
        }
    } else {
        const int r = tid >> 3;
        const int fc = (tid & 7) * 16;
        const int node = n0 + r;
        const float dd = g_d[c * N + node];
        const float* sp = g_Sp + ((size_t)(c * N + node)) * F;
        float* op = out + (size_t)node * (C * F) + c * F;
        #pragma unroll
        for (int j0 = 0; j0 < 16; j0 += 4) {
            float4 a4 = *(float4*)&smf[r * 132 + fc + j0];
            float4 s4 = *(const float4*)(sp + fc + j0);
            float4 b4 = *(const float4*)(bias + fc + j0);
            float4 o;
            o.x = fmaxf(dd * (a4.x + s4.x) + b4.x, 0.f);
            o.y = fmaxf(dd * (a4.y + s4.y) + b4.y, 0.f);
            o.z = fmaxf(dd * (a4.z + s4.z) + b4.z, 0.f);
            o.w = fmaxf(dd * (a4.w + s4.w) + b4.w, 0.f);
            *(float4*)(op + fc + j0) = o;
        }
    }
}

// ---------------- launcher ----------------
extern "C" void kernel_launch(void* const* d_in, const int* in_sizes, int n_in,
                              void* d_out, int out_size) {
    const float* A  = (const float*)d_in[0];   // [E,N,N]
    const float* X  = (const float*)d_in[1];   // [N,WIN]
    const float* w1 = (const float*)d_in[2];   // [C,E]
    const float* w2 = (const float*)d_in[3];   // [C,E]
    const float* w3 = (const float*)d_in[4];   // [C,C]
    const float* gw = (const float*)d_in[5];   // [WIN,F]
    const float* gb = (const float*)d_in[6];   // [F]
    float* out = (float*)d_out;                // [N, C*F]

    static bool attr_done = false;
    if (!attr_done) {
        cudaFuncSetAttribute(k_gemm_hp, cudaFuncAttributeMaxDynamicSharedMemorySize,
                             GEMM_SMEM);
        attr_done = true;
    }

    k_softmax<<<1, 32>>>(w1, w2, w3);
    k_premix_h<<<dim3(16, 128), 256>>>(A);       // 12 fp16 frag planes + partial rowsums
    k_support<<<N / 32, 256>>>(X, gw);           // support + fused mix_v1
    k_matvec_h<<<dim3(128, 4), 256>>>(0);        // v2 partials (fp16 planes, split-k)
    k_matvec_h<<<dim3(128, 4), 256>>>(1);        // v3 partials
    k_dSp_h<<<N / 16, 256>>>();                  // d (sums v3 partials), Sp, SpB
    k_gemm_hp<<<dim3(N / 64, C), 512, GEMM_SMEM>>>(gb, out, 0);   // T0B
    k_gemm_hp<<<dim3(N / 64, C), 512, GEMM_SMEM>>>(gb, out, 1);   // T1B
    k_gemm_hp<<<dim3(N / 64, C), 512, GEMM_SMEM>>>(gb, out, 2);   // out
}

// round 15
// speedup vs baseline: 1.7756x; 1.0345x over previous
#include <cuda_runtime.h>
#include <cuda_fp16.h>
#include <cstdint>

#define N 2048
#define E 4
#define C 4
#define F 128      // W_OUT
#define WIN 256
#define NNSZ ((size_t)N * N)
#define NFSZ ((size_t)N * F)
#define SPB_SCALE 1024.0f
#define SPB_UNSCALE (1.0f / 1024.0f)

// ---------------- scratch (static device globals; no allocation) ----------------
__device__ float g_fw[3][16];            // softmaxed weights: [0]=fw1, [1]=fw2, [2]=fw3
__device__ float g_support[N * F];       // X @ gcn_w              [n][f]
__device__ float g_part[16 * E * N];     // per-chunk partial raw rowsums
__device__ float g_v1[C * N];
__device__ float g_v2p[4][C * N];        // split-k partials of v2
__device__ float g_v3p[4][C * N];        // split-k partials of v3
__device__ float g_d[C * N];             // deg^-1/2
__device__ float g_Sp[C * N * F];        // diag(d)@support natural [c][n][f] fp32
// fp16 fragment-order planes
__device__ __align__(16) __half g_SpBH[C * N * F];   // B plane stage 0 (scaled x1024)
__device__ __align__(16) __half g_T0BH[C * N * F];   // B plane stage 1 (natural)
__device__ __align__(16) __half g_T1BH[C * N * F];   // B plane stage 2 (natural)
// premixed A planes fp16: [stage*4+c], unit = m16 x k16 (256 halfs); unit idx = mt*128 + kt
__device__ __align__(16) __half g_AmH[12 * NNSZ];    // 96 MB

__device__ __forceinline__ uint32_t pkh(float a, float b) {
    __half2 h = __floats2half2_rn(a, b);
    return *(uint32_t*)&h;
}

// mma.m16n8k16 f16 -> f32 accum
__device__ __forceinline__ void mma_f16(float& d0, float& d1, float& d2, float& d3,
                                        uint32_t a0, uint32_t a1, uint32_t a2, uint32_t a3,
                                        uint32_t b0, uint32_t b1) {
    asm volatile(
        "mma.sync.aligned.m16n8k16.row.col.f32.f16.f16.f32 "
        "{%0,%1,%2,%3}, {%4,%5,%6,%7}, {%8,%9}, {%0,%1,%2,%3};"
        : "+f"(d0), "+f"(d1), "+f"(d2), "+f"(d3)
        : "r"(a0), "r"(a1), "r"(a2), "r"(a3), "r"(b0), "r"(b1));
}

__device__ __forceinline__ void cp_async16(uint32_t s, const void* g) {
    asm volatile("cp.async.ca.shared.global [%0], [%1], 16;" :: "r"(s), "l"(g));
}
__device__ __forceinline__ void cp_commit() { asm volatile("cp.async.commit_group;"); }
__device__ __forceinline__ void cp_wait2() { asm volatile("cp.async.wait_group 2;"); }
__device__ __forceinline__ void cp_wait0() { asm volatile("cp.async.wait_group 0;"); }

// ---------------- tiny: softmax of 4x4 weight rows ----------------
__global__ void k_softmax(const float* __restrict__ w1,
                          const float* __restrict__ w2,
                          const float* __restrict__ w3) {
    int t = threadIdx.x;
    if (t >= 12) return;
    int mat = t >> 2, row = t & 3;
    const float* src = (mat == 0) ? w1 : (mat == 1) ? w2 : w3;
    float a0 = src[row * 4 + 0], a1 = src[row * 4 + 1];
    float a2 = src[row * 4 + 2], a3 = src[row * 4 + 3];
    float mx = fmaxf(fmaxf(a0, a1), fmaxf(a2, a3));
    float e0 = expf(a0 - mx), e1 = expf(a1 - mx), e2 = expf(a2 - mx), e3 = expf(a3 - mx);
    float inv = 1.0f / (e0 + e1 + e2 + e3);
    g_fw[mat][row * 4 + 0] = e0 * inv;
    g_fw[mat][row * 4 + 1] = e1 * inv;
    g_fw[mat][row * 4 + 2] = e2 * inv;
    g_fw[mat][row * 4 + 3] = e3 * inv;
}

// ---------------- support = X @ gcn_w  (+ fused mix_v1 tail) ----------------
__global__ void __launch_bounds__(256) k_support(const float* __restrict__ X,
                                                 const float* __restrict__ W) {
    __shared__ float Xs[32][WIN];
    __shared__ float rsum[32][4];
    int tid = threadIdx.x;
    int row0 = blockIdx.x * 32;
    const float4* Xg = (const float4*)(X + (size_t)row0 * WIN);
    float4* Xs4 = (float4*)&Xs[0][0];
    #pragma unroll
    for (int j = 0; j < (32 * WIN / 4) / 256; j++)
        Xs4[tid + j * 256] = Xg[tid + j * 256];

    if (tid < 128) {
        int r = tid >> 2, e = tid & 3;
        float s = 0.f;
        #pragma unroll
        for (int ch = 0; ch < 16; ch++)
            s += g_part[(size_t)ch * (4 * N) + e * N + row0 + r];
        rsum[r][e] = s;
    }
    __syncthreads();
    if (tid < 32) {
        int r = tid;
        #pragma unroll
        for (int c = 0; c < 4; c++)
            g_v1[c * N + row0 + r] =
                g_fw[2][c * 4 + 0] * rsum[r][0] + g_fw[2][c * 4 + 1] * rsum[r][1]
              + g_fw[2][c * 4 + 2] * rsum[r][2] + g_fw[2][c * 4 + 3] * rsum[r][3];
    }

    int f = tid & 127, ty = tid >> 7;
    float acc[16];
    #pragma unroll
    for (int r = 0; r < 16; r++) acc[r] = 0.f;
    for (int k = 0; k < WIN; k++) {
        float w = W[k * F + f];
        #pragma unroll
        for (int r = 0; r < 16; r++)
            acc[r] = fmaf(Xs[ty * 16 + r][k], w, acc[r]);
    }
    #pragma unroll
    for (int r = 0; r < 16; r++)
        g_support[(size_t)(row0 + ty * 16 + r) * F + f] = acc[r];
}

// ---------------- premix fp16: one (band, chunk) tile per CTA ----------------
__global__ void __launch_bounds__(256) k_premix_h(const float* __restrict__ A) {
    __shared__ float As[4][16][132];
    __shared__ float wsm[48];
    const int tid = threadIdx.x, lane = tid & 31, warp = tid >> 5;
    const int g = lane >> 2, cl = lane & 3;
    const int ch = blockIdx.x;
    const int band = blockIdx.y;
    const int n0 = band * 16, m0 = ch * 128;

    if (tid < 48) wsm[tid] = ((const float*)g_fw)[tid];
    #pragma unroll
    for (int e = 0; e < 4; e++)
        #pragma unroll
        for (int j = 0; j < 2; j++) {
            int idx = tid + j * 256;
            int r = idx >> 5, m4 = idx & 31;
            *(float4*)&As[e][r][m4 * 4] =
                *(const float4*)(A + (size_t)e * NNSZ + (size_t)(n0 + r) * N + m0 + m4 * 4);
        }
    __syncthreads();

    {
        int e = tid >> 6, r = (tid >> 2) & 15, part = tid & 3;
        float s = 0.f;
        #pragma unroll
        for (int i = 0; i < 32; i++) s += As[e][r][part * 32 + i];
        s += __shfl_xor_sync(0xffffffffu, s, 1);
        s += __shfl_xor_sync(0xffffffffu, s, 2);
        if (part == 0) g_part[(size_t)ch * (4 * N) + e * N + n0 + r] = s;
    }

    for (int task = warp; task < 96; task += 8) {
        int plane = task >> 3, ktl = task & 7;
        int s = plane >> 2;
        const float* wv = wsm + (2 - s) * 16 + (plane & 3) * 4;
        int cols[4] = {ktl * 16 + 2 * cl, ktl * 16 + 2 * cl + 1,
                       ktl * 16 + 2 * cl + 8, ktl * 16 + 2 * cl + 9};
        float m[8];
        #pragma unroll
        for (int j = 0; j < 4; j++) {
            float lo = 0.f, hi = 0.f;
            #pragma unroll
            for (int e = 0; e < 4; e++) {
                lo = fmaf(wv[e], As[e][g][cols[j]], lo);
                hi = fmaf(wv[e], As[e][g + 8][cols[j]], hi);
            }
            m[j * 2] = lo; m[j * 2 + 1] = hi;
        }
        uint4 u;
        u.x = pkh(m[0], m[2]);
        u.y = pkh(m[1], m[3]);
        u.z = pkh(m[4], m[6]);
        u.w = pkh(m[5], m[7]);
        size_t unit = (size_t)band * 128 + ch * 8 + ktl;
        *(uint4*)(g_AmH + (size_t)plane * NNSZ + unit * 256 + lane * 8) = u;
    }
}

// ---------------- matvec on fp16 premixed planes, split-k ----------------
__global__ void __launch_bounds__(256) k_matvec_h(int stage) {
    __shared__ float vs[4][512];
    __shared__ float red[8][16][4];
    const int tid = threadIdx.x, lane = tid & 31, warp = tid >> 5;
    const int band = blockIdx.x, ks = blockIdx.y;
    const int g = lane >> 2, cl = lane & 3;

    if (stage == 0) {
        #pragma unroll
        for (int i = 0; i < 2; i++) {
            int idx = tid + i * 256;
            int c = idx >> 7, m4 = (idx & 127) * 4;
            *(float4*)&vs[c][m4] = *(const float4*)(g_v1 + c * N + ks * 512 + m4);
        }
    } else {
        #pragma unroll
        for (int i = 0; i < 2; i++) {
            int idx = tid + i * 256;
            int c = idx >> 7, m4 = (idx & 127) * 4;
            float4 s = *(const float4*)(g_v2p[0] + c * N + ks * 512 + m4);
            #pragma unroll
            for (int p = 1; p < 4; p++) {
                float4 t = *(const float4*)(g_v2p[p] + c * N + ks * 512 + m4);
                s.x += t.x; s.y += t.y; s.z += t.z; s.w += t.w;
            }
            *(float4*)&vs[c][m4] = s;
        }
    }
    __syncthreads();

    const uint4* __restrict__ P = (const uint4*)(g_AmH + (size_t)(stage + 1) * 4 * NNSZ);
    const size_t PST = NNSZ / 8;

    float acc0[4] = {0.f, 0.f, 0.f, 0.f};
    float acc1[4] = {0.f, 0.f, 0.f, 0.f};
    #pragma unroll
    for (int j = 0; j < 4; j++) {
        int ktl = warp * 4 + j;
        size_t bi = ((size_t)band * 128 + ks * 32 + ktl) * 32 + lane;
        int mL = ktl * 16 + 2 * cl;
        #pragma unroll
        for (int c = 0; c < 4; c++) {
            uint4 u = P[bi + (size_t)c * PST];
            float vx = vs[c][mL], vy = vs[c][mL + 1];
            float vz = vs[c][mL + 8], vw = vs[c][mL + 9];
            float2 hx = __half22float2(*(__half2*)&u.x);
            float2 hy = __half22float2(*(__half2*)&u.y);
            float2 hz = __half22float2(*(__half2*)&u.z);
            float2 hw = __half22float2(*(__half2*)&u.w);
            acc0[c] = fmaf(hx.x, vx, fmaf(hx.y, vy, fmaf(hz.x, vz, fmaf(hz.y, vw, acc0[c]))));
            acc1[c] = fmaf(hy.x, vx, fmaf(hy.y, vy, fmaf(hw.x, vz, fmaf(hw.y, vw, acc1[c]))));
        }
    }
    #pragma unroll
    for (int d = 1; d <= 2; d <<= 1)
        #pragma unroll
        for (int c = 0; c < 4; c++) {
            acc0[c] += __shfl_xor_sync(0xffffffffu, acc0[c], d);
            acc1[c] += __shfl_xor_sync(0xffffffffu, acc1[c], d);
        }
    if (cl == 0) {
        #pragma unroll
        for (int c = 0; c < 4; c++) {
            red[warp][g][c] = acc0[c];
            red[warp][g + 8][c] = acc1[c];
        }
    }
    __syncthreads();
    float* vout = (stage == 0) ? g_v2p[ks] : g_v3p[ks];
    if (tid < 64) {
        int row = tid >> 2, c = tid & 3;
        float s = 0.f;
        #pragma unroll
        for (int wv = 0; wv < 8; wv++) s += red[wv][row][c];
        vout[c * N + band * 16 + row] = s;
    }
}

// ---------------- d, Sp natural fp32, SpB fp16 scaled (fragment B-units) ----------------
__global__ void __launch_bounds__(256) k_dSp_h() {
    __shared__ float sup[16][132];
    __shared__ float dsm[4][16];
    const int tid = threadIdx.x;
    const int k0 = blockIdx.x * 16;
    {
        int r = tid >> 4, f8 = (tid & 15) * 8;
        *(float4*)&sup[r][f8] = *(const float4*)(g_support + (size_t)(k0 + r) * F + f8);
        *(float4*)&sup[r][f8 + 4] = *(const float4*)(g_support + (size_t)(k0 + r) * F + f8 + 4);
    }
    if (tid < 64) {
        int c = tid >> 4, kk = tid & 15;
        float v3 = g_v3p[0][c * N + k0 + kk] + g_v3p[1][c * N + k0 + kk]
                 + g_v3p[2][c * N + k0 + kk] + g_v3p[3][c * N + k0 + kk];
        float deg = v3 + 1.0f;
        float d = (deg > 0.f) ? rsqrtf(deg) : 0.f;
        dsm[c][kk] = d;
        g_d[c * N + k0 + kk] = d;
    }
    __syncthreads();
    {
        int r = tid >> 4, f8 = (tid & 15) * 8;
        float4 s0 = *(float4*)&sup[r][f8];
        float4 s1 = *(float4*)&sup[r][f8 + 4];
        #pragma unroll
        for (int c = 0; c < 4; c++) {
            float d = dsm[c][r];
            float4 o0 = make_float4(d * s0.x, d * s0.y, d * s0.z, d * s0.w);
            float4 o1 = make_float4(d * s1.x, d * s1.y, d * s1.z, d * s1.w);
            *(float4*)(g_Sp + ((size_t)c * N + k0 + r) * F + f8) = o0;
            *(float4*)(g_Sp + ((size_t)c * N + k0 + r) * F + f8 + 4) = o1;
        }
    }
    {
        int nt = tid >> 5, l = tid & 31;
        int g = l >> 2, cl = l & 3;
        int na = nt * 16 + g, nb = na + 8;
        int ka = 2 * cl, kb = 2 * cl + 8;
        #pragma unroll
        for (int c = 0; c < 4; c++) {
            float d0 = dsm[c][ka] * SPB_SCALE,     d1 = dsm[c][ka + 1] * SPB_SCALE;
            float d8 = dsm[c][kb] * SPB_SCALE,     d9 = dsm[c][kb + 1] * SPB_SCALE;
            uint4 u;
            u.x = pkh(d0 * sup[ka][na], d1 * sup[ka + 1][na]);
            u.y = pkh(d8 * sup[kb][na], d9 * sup[kb + 1][na]);
            u.z = pkh(d0 * sup[ka][nb], d1 * sup[ka + 1][nb]);
            u.w = pkh(d8 * sup[kb][nb], d9 * sup[kb + 1][nb]);
            *(uint4*)(g_SpBH + (size_t)c * NFSZ + ((size_t)blockIdx.x * 8 + nt) * 256 + l * 8) = u;
        }
    }
}

// ---------------- main GEMM: fp16 m16n8k16, 256 threads, warp tile 32x32 ----------------
// cp.async depth-4 x k64 groups (24 KB each, 96 KB total). grid (32, 4).
#define GQ 1536
#define GEMM_SMEM (4 * GQ * 16)

__global__ void __launch_bounds__(256) k_gemm_hp(const float* __restrict__ bias,
                                                 float* __restrict__ out, int stage) {
    extern __shared__ uint4 smp[];
    const int tid = threadIdx.x, lane = tid & 31, warp = tid >> 5;   // 8 warps
    const int wm = warp >> 2, wn = warp & 3;       // 2 x 4 warps, warp tile 32x32
    const int c = blockIdx.y;
    const int bx = blockIdx.x;
    const int n0 = bx * 64;
    const int g = lane >> 2, cl = lane & 3;

    const uint4* __restrict__ Aplane = (const uint4*)(g_AmH + (size_t)(stage * 4 + c) * NNSZ);
    const uint4* __restrict__ Bplane = (const uint4*)(((stage == 0) ? g_SpBH :
                                        (stage == 1) ? g_T0BH : g_T1BH) + (size_t)c * NFSZ);
    const uint32_t sbase = (uint32_t)__cvta_generic_to_shared(smp);

    float acc[2][4][4];
    #pragma unroll
    for (int i = 0; i < 2; i++)
        #pragma unroll
        for (int j = 0; j < 4; j++)
            #pragma unroll
            for (int q = 0; q < 4; q++) acc[i][j][q] = 0.f;

    // prologue: groups 0..2 (256 threads: A 2 chunks, B 4 chunks per thread)
    #pragma unroll
    for (int p = 0; p < 3; p++) {
        uint32_t gb = sbase + (uint32_t)(p * GQ) * 16;
        #pragma unroll
        for (int q = 0; q < 2; q++) {
            int idx = tid + q * 256;
            int ktl = idx >> 7, mu = (idx >> 5) & 3, ln = idx & 31;
            cp_async16(gb + (uint32_t)((ktl * 4 + mu) * 32 + ln) * 16,
                       Aplane + ((size_t)(bx * 4 + mu) * 128 + (size_t)(4 * p + ktl)) * 32 + ln);
        }
        #pragma unroll
        for (int q = 0; q < 4; q++) {
            int idx = tid + q * 256;
            int ktl = idx >> 8, nu = (idx >> 5) & 7, ln = idx & 31;
            cp_async16(gb + (uint32_t)(512 + (ktl * 8 + nu) * 32 + ln) * 16,
                       Bplane + ((size_t)(4 * p + ktl) * 8 + nu) * 32 + ln);
        }
        cp_commit();
    }

    for (int gr = 0; gr < 32; gr++) {
        cp_wait2();
        __syncthreads();
        if (gr + 3 < 32) {
            uint32_t gb = sbase + (uint32_t)(((gr + 3) & 3) * GQ) * 16;
            #pragma unroll
            for (int q = 0; q < 2; q++) {
                int idx = tid + q * 256;
                int ktl = idx >> 7, mu = (idx >> 5) & 3, ln = idx & 31;
                cp_async16(gb + (uint32_t)((ktl * 4 + mu) * 32 + ln) * 16,
                           Aplane + ((size_t)(bx * 4 + mu) * 128 + (size_t)(4 * (gr + 3) + ktl)) * 32 + ln);
            }
            #pragma unroll
            for (int q = 0; q < 4; q++) {
                int idx = tid + q * 256;
                int ktl = idx >> 8, nu = (idx >> 5) & 7, ln = idx & 31;
                cp_async16(gb + (uint32_t)(512 + (ktl * 8 + nu) * 32 + ln) * 16,
                           Bplane + ((size_t)(4 * (gr + 3) + ktl) * 8 + nu) * 32 + ln);
            }
        }
        cp_commit();

        const uint4* Ab = smp + (size_t)(gr & 3) * GQ;
        const uint4* Bb = Ab + 512;
        #pragma unroll
        for (int j = 0; j < 4; j++) {
            uint4 a0 = Ab[(j * 4 + wm * 2) * 32 + lane];
            uint4 a1 = Ab[(j * 4 + wm * 2 + 1) * 32 + lane];
            uint4 b0 = Bb[(j * 8 + wn * 2) * 32 + lane];
            uint4 b1 = Bb[(j * 8 + wn * 2 + 1) * 32 + lane];
            #pragma unroll
            for (int i = 0; i < 2; i++) {
                uint4 a = (i == 0) ? a0 : a1;
                mma_f16(acc[i][0][0], acc[i][0][1], acc[i][0][2], acc[i][0][3],
                        a.x, a.y, a.z, a.w, b0.x, b0.y);
                mma_f16(acc[i][1][0], acc[i][1][1], acc[i][1][2], acc[i][1][3],
                        a.x, a.y, a.z, a.w, b0.z, b0.w);
                mma_f16(acc[i][2][0], acc[i][2][1], acc[i][2][2], acc[i][2][3],
                        a.x, a.y, a.z, a.w, b1.x, b1.y);
                mma_f16(acc[i][3][0], acc[i][3][1], acc[i][3][2], acc[i][3][3],
                        a.x, a.y, a.z, a.w, b1.z, b1.w);
            }
        }
    }

    cp_wait0();
    __syncthreads();

    // park D in smem (natural [node][f]) — reuse pipeline smem
    float* smf = (float*)smp;
    {
        #pragma unroll
        for (int i = 0; i < 2; i++)
            #pragma unroll
            for (int j = 0; j < 4; j++) {
                int row = wm * 32 + i * 16 + g;
                int col = wn * 32 + j * 8 + 2 * cl;
                smf[row * 132 + col] = acc[i][j][0];
                smf[row * 132 + col + 1] = acc[i][j][1];
                smf[(row + 8) * 132 + col] = acc[i][j][2];
                smf[(row + 8) * 132 + col + 1] = acc[i][j][3];
            }
    }
    __syncthreads();

    if (stage < 2) {
        const float scl = (stage == 0) ? SPB_UNSCALE : 1.0f;
        __half* __restrict__ Bout = ((stage == 0) ? g_T0BH : g_T1BH) + (size_t)c * NFSZ;
        #pragma unroll
        for (int q = 0; q < 4; q++) {
            int uu = warp * 4 + q;
            int ku = uu >> 3, nu = uu & 7;
            int kb2 = ku * 16;
            int na = nu * 16 + g, nb = na + 8;
            int ka = kb2 + 2 * cl, kc = kb2 + 2 * cl + 8;
            uint4 u;
            u.x = pkh(scl * smf[ka * 132 + na],     scl * smf[(ka + 1) * 132 + na]);
            u.y = pkh(scl * smf[kc * 132 + na],     scl * smf[(kc + 1) * 132 + na]);
            u.z = pkh(scl * smf[ka * 132 + nb],     scl * smf[(ka + 1) * 132 + nb]);
            u.w = pkh(scl * smf[kc * 132 + nb],     scl * smf[(kc + 1) * 132 + nb]);
            *(uint4*)(Bout + ((size_t)(bx * 4 + ku) * 8 + nu) * 256 + lane * 8) = u;
        }
    } else {
        const int r = tid >> 2;
        const int fc = (tid & 3) * 32;
        const int node = n0 + r;
        const float dd = g_d[c * N + node];
        const float* sp = g_Sp + ((size_t)(c * N + node)) * F;
        float* op = out + (size_t)node * (C * F) + c * F;
        #pragma unroll
        for (int j0 = 0; j0 < 32; j0 += 4) {
            float4 a4 = *(float4*)&smf[r * 132 + fc + j0];
            float4 s4 = *(const float4*)(sp + fc + j0);
            float4 b4 = *(const float4*)(bias + fc + j0);
            float4 o;
            o.x = fmaxf(dd * (a4.x + s4.x) + b4.x, 0.f);
            o.y = fmaxf(dd * (a4.y + s4.y) + b4.y, 0.f);
            o.z = fmaxf(dd * (a4.z + s4.z) + b4.z, 0.f);
            o.w = fmaxf(dd * (a4.w + s4.w) + b4.w, 0.f);
            *(float4*)(op + fc + j0) = o;
        }
    }
}

// ---------------- launcher ----------------
extern "C" void kernel_launch(void* const* d_in, const int* in_sizes, int n_in,
                              void* d_out, int out_size) {
    const float* A  = (const float*)d_in[0];   // [E,N,N]
    const float* X  = (const float*)d_in[1];   // [N,WIN]
    const float* w1 = (const float*)d_in[2];   // [C,E]
    const float* w2 = (const float*)d_in[3];   // [C,E]
    const float* w3 = (const float*)d_in[4];   // [C,C]
    const float* gw = (const float*)d_in[5];   // [WIN,F]
    const float* gb = (const float*)d_in[6];   // [F]
    float* out = (float*)d_out;                // [N, C*F]

    static bool attr_done = false;
    if (!attr_done) {
        cudaFuncSetAttribute(k_gemm_hp, cudaFuncAttributeMaxDynamicSharedMemorySize,
                             GEMM_SMEM);
        attr_done = true;
    }

    k_softmax<<<1, 32>>>(w1, w2, w3);
    k_premix_h<<<dim3(16, 128), 256>>>(A);       // 12 fp16 frag planes + partial rowsums
    k_support<<<N / 32, 256>>>(X, gw);           // support + fused mix_v1
    k_matvec_h<<<dim3(128, 4), 256>>>(0);        // v2 partials
    k_matvec_h<<<dim3(128, 4), 256>>>(1);        // v3 partials
    k_dSp_h<<<N / 16, 256>>>();                  // d, Sp, SpB
    k_gemm_hp<<<dim3(N / 64, C), 256, GEMM_SMEM>>>(gb, out, 0);   // T0B
    k_gemm_hp<<<dim3(N / 64, C), 256, GEMM_SMEM>>>(gb, out, 1);   // T1B
    k_gemm_hp<<<dim3(N / 64, C), 256, GEMM_SMEM>>>(gb, out, 2);   // out
}